// round 9
// baseline (speedup 1.0000x reference)
#include <cuda_runtime.h>
#include <cuda_bf16.h>
#include <math.h>

#define MTOK 262144   // B*H*W = 4*256*256
#define CDIM 128
#define HID  512

// ---------------- scratch (device globals: allocation-free) ----------------
__device__ __nv_bfloat16 g_xw[(size_t)MTOK*CDIM];  // LN1 + shift + window partition
__device__ __nv_bfloat16 g_q [(size_t)MTOK*CDIM];
__device__ __nv_bfloat16 g_k [(size_t)MTOK*CDIM];
__device__ __nv_bfloat16 g_v [(size_t)MTOK*CDIM];
__device__ __nv_bfloat16 g_ao[(size_t)MTOK*CDIM];  // attention output (window order)
__device__ __nv_bfloat16 g_dl[(size_t)MTOK*CDIM];  // delta = proj_out + bias (bf16, window order)
__device__ __nv_bfloat16 g_l2[(size_t)MTOK*CDIM];  // LN2(hs[perm] + delta)
__device__ __nv_bfloat16 g_wt[196608];             // transposed bf16 weights [N][K]

__device__ __forceinline__ int region(int a) { return a < 248 ? 0 : (a < 252 ? 1 : 2); }

__device__ __forceinline__ void mma_bf16(float c[4], const unsigned a[4], const unsigned b[2]) {
    asm volatile("mma.sync.aligned.m16n8k16.row.col.f32.bf16.bf16.f32 "
        "{%0,%1,%2,%3}, {%4,%5,%6,%7}, {%8,%9}, {%0,%1,%2,%3};\n"
        : "+f"(c[0]), "+f"(c[1]), "+f"(c[2]), "+f"(c[3])
        : "r"(a[0]), "r"(a[1]), "r"(a[2]), "r"(a[3]), "r"(b[0]), "r"(b[1]));
}
__device__ __forceinline__ void cp16(unsigned dst, const void* src) {
    asm volatile("cp.async.cg.shared.global [%0], [%1], 16;\n" :: "r"(dst), "l"(src));
}
#define CP_COMMIT asm volatile("cp.async.commit_group;\n" ::: "memory")
#define CP_WAIT1  asm volatile("cp.async.wait_group 1;\n" ::: "memory")
#define CP_WAIT0  asm volatile("cp.async.wait_group 0;\n" ::: "memory")

// window-order index m -> original token index (window reverse + roll(+4,+4))
__device__ __forceinline__ int perm_m(int m) {
    int b = m >> 16, w = (m >> 6) & 1023, t = m & 63;
    int wh = w >> 5, ww = w & 31, ti = t >> 3, tj = t & 7;
    int r = (wh*8 + ti + 4) & 255;
    int c = (ww*8 + tj + 4) & 255;
    return (b << 16) | (r << 8) | c;
}
__device__ __forceinline__ unsigned packbf(float a, float b) {
    __nv_bfloat162 t = __floats2bfloat162_rn(a, b);
    return *(unsigned*)&t;
}

// ---------------- fused weight prep: all six matrices in one launch --------
__global__ void prep_all(const float* __restrict__ qw, const float* __restrict__ kw,
                         const float* __restrict__ vw, const float* __restrict__ pw,
                         const float* __restrict__ f1w, const float* __restrict__ f2w,
                         __nv_bfloat16* __restrict__ wt)
{
    int idx = blockIdx.x * 256 + threadIdx.x;     // 0..196607
    float v;
    if (idx < 65536) {
        int seg = idx >> 14;
        int rel = idx & 16383;
        int n = rel >> 7, k = rel & 127;
        const float* src = seg == 0 ? qw : (seg == 1 ? kw : (seg == 2 ? vw : pw));
        v = src[k*128 + n];
    } else if (idx < 131072) {
        int rel = idx - 65536;            // f1t [512][128] <- f1w [128][512]
        int n = rel >> 7, k = rel & 127;
        v = f1w[k*512 + n];
    } else {
        int rel = idx - 131072;           // f2t [128][512] <- f2w [512][128]
        int n = rel >> 9, k = rel & 511;
        v = f2w[k*128 + n];
    }
    wt[idx] = __float2bfloat16(v);
}

// ---------------- LayerNorm (fused with shift+window gather), bf16 out -----
__global__ void ln_kernel(const float* __restrict__ in, const float* __restrict__ gamma,
                          const float* __restrict__ beta, __nv_bfloat16* __restrict__ out,
                          int gather)
{
    int token = blockIdx.x * 8 + (threadIdx.x >> 5);
    int lane  = threadIdx.x & 31;
    int src = gather ? perm_m(token) : token;
    float4 xv = ((const float4*)in)[(size_t)src*32 + lane];
    float s  = xv.x + xv.y + xv.z + xv.w;
    float sq = xv.x*xv.x + xv.y*xv.y + xv.z*xv.z + xv.w*xv.w;
    #pragma unroll
    for (int o = 16; o; o >>= 1) {
        s  += __shfl_xor_sync(0xffffffffu, s,  o);
        sq += __shfl_xor_sync(0xffffffffu, sq, o);
    }
    float mean = s * (1.f/128.f);
    float var  = sq * (1.f/128.f) - mean*mean;
    float rstd = rsqrtf(var + 1e-5f);
    float4 g  = ((const float4*)gamma)[lane];
    float4 bt = ((const float4*)beta)[lane];
    uint2 pk;
    pk.x = packbf((xv.x - mean)*rstd*g.x + bt.x, (xv.y - mean)*rstd*g.y + bt.y);
    pk.y = packbf((xv.z - mean)*rstd*g.z + bt.z, (xv.w - mean)*rstd*g.w + bt.w);
    ((uint2*)out)[(size_t)token*32 + lane] = pk;
}

// ---------------- bf16 tensor-core GEMM (QKV / proj+LN2) -------------------
#define BM 128
#define BN 128
#define BK 32
#define ASTR 20
#define BSTR 20
#define NST 3
#define SA_W (BM*ASTR)
#define SB_W (BN*BSTR)
#define GEMM_SMEM ((NST*(SA_W + SB_W))*4 + BM*4*4*2)

__global__ void __launch_bounds__(256, 2) gemm_tc(
    const __nv_bfloat16* __restrict__ A,
    const __nv_bfloat16* __restrict__ W0, const float* __restrict__ B0, void* __restrict__ C0v,
    const __nv_bfloat16* __restrict__ W1, const float* __restrict__ B1, void* __restrict__ C1v,
    const __nv_bfloat16* __restrict__ W2, const float* __restrict__ B2, void* __restrict__ C2v,
    int N, int K, float scale, int mode,
    const float* __restrict__ add, __nv_bfloat16* __restrict__ aux_bf,
    const float* __restrict__ gamma, const float* __restrict__ beta)
{
    extern __shared__ unsigned smem[];
    unsigned* AsB = smem;
    unsigned* BsB = smem + NST*SA_W;
    float* red_s = (float*)(smem + NST*(SA_W + SB_W));
    float* red_q = red_s + BM*4;

    const int tid  = threadIdx.x;
    const int lane = tid & 31;
    const int lr   = lane >> 2;
    const int lc   = lane & 3;
    const int w    = tid >> 5;
    const int wm   = w >> 2;
    const int wn   = w & 3;
    const int m0   = blockIdx.y * BM;

    const __nv_bfloat16* Bw; const float* bias; void* Cout; float sc; int n0;
    if (mode == 0) {
        int s = blockIdx.x;
        Bw   = s == 0 ? W0 : (s == 1 ? W1 : W2);
        bias = s == 0 ? B0 : (s == 1 ? B1 : B2);
        Cout = s == 0 ? C0v : (s == 1 ? C1v : C2v);
        sc   = s == 0 ? scale : 1.0f;
        n0   = 0;
    } else {
        Bw = W0; bias = B0; Cout = C0v; sc = 1.0f;
        n0 = blockIdx.x * BN;
    }

    const int grow = tid >> 2;
    const int gc8  = (tid & 3) << 3;

    const __nv_bfloat16* Ap0 = A  + (size_t)(m0 + grow) * K + gc8;
    const __nv_bfloat16* Ap1 = Ap0 + (size_t)64 * K;
    const __nv_bfloat16* Bp0 = Bw + (size_t)(n0 + grow) * K + gc8;
    const __nv_bfloat16* Bp1 = Bp0 + (size_t)64 * K;

    const unsigned a_base = (unsigned)__cvta_generic_to_shared(AsB);
    const unsigned b_base = (unsigned)__cvta_generic_to_shared(BsB);
    const unsigned a_s0 = a_base + (grow*ASTR + (tid & 3)*4)*4;
    const unsigned a_s1 = a_base + ((grow+64)*ASTR + (tid & 3)*4)*4;
    const unsigned b_s0 = b_base + (grow*BSTR + (tid & 3)*4)*4;
    const unsigned b_s1 = b_base + ((grow+64)*BSTR + (tid & 3)*4)*4;
    const unsigned SAB = SA_W*4, SBB = SB_W*4;

    const int stages = K >> 5;

    #define ISSUE(t, buf) { \
        int kt_ = (t) << 5; \
        cp16(a_s0 + (buf)*SAB, Ap0 + kt_); \
        cp16(a_s1 + (buf)*SAB, Ap1 + kt_); \
        cp16(b_s0 + (buf)*SBB, Bp0 + kt_); \
        cp16(b_s1 + (buf)*SBB, Bp1 + kt_); \
        CP_COMMIT; }

    ISSUE(0, 0);
    ISSUE(1, 1);
    CP_WAIT1;
    __syncthreads();

    float acc[4][4][4];
    #pragma unroll
    for (int i = 0; i < 4; i++)
        #pragma unroll
        for (int j = 0; j < 4; j++)
            #pragma unroll
            for (int c = 0; c < 4; c++) acc[i][j][c] = 0.f;

    const int a_off = (wm*64 + lr)*ASTR + lc;
    const int b_off = (wn*32 + lr)*BSTR + lc;

    for (int t = 0; t < stages; t++) {
        const unsigned* as = AsB + (t % NST)*SA_W;
        const unsigned* bs = BsB + (t % NST)*SB_W;
        #pragma unroll
        for (int kk2 = 0; kk2 < 16; kk2 += 8) {
            unsigned afr[4][4];
            #pragma unroll
            for (int i = 0; i < 4; i++) {
                int base = a_off + i*16*ASTR + kk2;
                afr[i][0] = as[base];
                afr[i][1] = as[base + 8*ASTR];
                afr[i][2] = as[base + 4];
                afr[i][3] = as[base + 8*ASTR + 4];
            }
            #pragma unroll
            for (int j = 0; j < 4; j++) {
                unsigned bfr[2];
                int bb = b_off + j*8*BSTR + kk2;
                bfr[0] = bs[bb];
                bfr[1] = bs[bb + 4];
                #pragma unroll
                for (int i = 0; i < 4; i++)
                    mma_bf16(acc[i][j], afr[i], bfr);
            }
        }
        if (t + 2 < stages) {
            ISSUE(t + 2, (t + 2) % NST);
            CP_WAIT1;
            __syncthreads();
        } else if (t + 1 < stages) {
            CP_WAIT0;
            __syncthreads();
        }
    }
    #undef ISSUE

    // ---------------- epilogue ----------------
    if (mode == 1) {
        __nv_bfloat16* Cd = (__nv_bfloat16*)Cout;
        #pragma unroll
        for (int i = 0; i < 4; i++) {
            #pragma unroll
            for (int half = 0; half < 2; half++) {
                int rl = wm*64 + i*16 + lr + half*8;
                int m  = m0 + rl;
                const float* hsrow = add + (size_t)perm_m(m) * 128;
                size_t drow = (size_t)m * 128;
                float s = 0.f, sq = 0.f;
                #pragma unroll
                for (int j = 0; j < 4; j++) {
                    int n = wn*32 + j*8 + 2*lc;
                    float d0 = acc[i][j][half*2 + 0] + bias[n];
                    float d1 = acc[i][j][half*2 + 1] + bias[n+1];
                    *(unsigned*)&Cd[drow + n] = packbf(d0, d1);
                    float v0 = d0 + hsrow[n];
                    float v1 = d1 + hsrow[n+1];
                    acc[i][j][half*2 + 0] = v0;
                    acc[i][j][half*2 + 1] = v1;
                    s  += v0 + v1;
                    sq += v0*v0 + v1*v1;
                }
                s  += __shfl_xor_sync(0xffffffffu, s, 1);
                s  += __shfl_xor_sync(0xffffffffu, s, 2);
                sq += __shfl_xor_sync(0xffffffffu, sq, 1);
                sq += __shfl_xor_sync(0xffffffffu, sq, 2);
                if (lc == 0) { red_s[rl*4 + wn] = s; red_q[rl*4 + wn] = sq; }
            }
        }
        __syncthreads();
        #pragma unroll
        for (int i = 0; i < 4; i++) {
            #pragma unroll
            for (int half = 0; half < 2; half++) {
                int rl = wm*64 + i*16 + lr + half*8;
                float s  = red_s[rl*4+0] + red_s[rl*4+1] + red_s[rl*4+2] + red_s[rl*4+3];
                float sq = red_q[rl*4+0] + red_q[rl*4+1] + red_q[rl*4+2] + red_q[rl*4+3];
                float mu = s * (1.f/128.f);
                float var = sq * (1.f/128.f) - mu*mu;
                float rstd = rsqrtf(var + 1e-5f);
                size_t base = (size_t)(m0 + rl) * 128;
                #pragma unroll
                for (int j = 0; j < 4; j++) {
                    int n = wn*32 + j*8 + 2*lc;
                    float l0 = (acc[i][j][half*2 + 0] - mu)*rstd*gamma[n]   + beta[n];
                    float l1 = (acc[i][j][half*2 + 1] - mu)*rstd*gamma[n+1] + beta[n+1];
                    *(unsigned*)&aux_bf[base + n] = packbf(l0, l1);
                }
            }
        }
    } else {
        __nv_bfloat16* Cb = (__nv_bfloat16*)Cout;
        #pragma unroll
        for (int i = 0; i < 4; i++) {
            #pragma unroll
            for (int half = 0; half < 2; half++) {
                int m = m0 + wm*64 + i*16 + lr + half*8;
                size_t dstrow = (size_t)m * N;
                #pragma unroll
                for (int j = 0; j < 4; j++) {
                    int n = wn*32 + j*8 + 2*lc;
                    int ng = n0 + n;
                    float v0 = (acc[i][j][half*2 + 0] + bias[ng]) * sc;
                    float v1 = (acc[i][j][half*2 + 1] + bias[ng+1]) * sc;
                    *(unsigned*)&Cb[dstrow + ng] = packbf(v0, v1);
                }
            }
        }
    }
}

// ---------------- fused MLP: fc1 + GELU (smem h) + fc2 + residuals ---------
#define ASTR2 68
#define HSTR  260
#define BSTR2 20
#define MLP_SMEM ((64*ASTR2 + 64*HSTR + 2*128*BSTR2)*4)

__global__ void __launch_bounds__(256, 2) mlp_fused(
    const __nv_bfloat16* __restrict__ A,
    const __nv_bfloat16* __restrict__ W1t,
    const float* __restrict__ b1,
    const __nv_bfloat16* __restrict__ W2t,
    const float* __restrict__ b2,
    const float* __restrict__ hs,
    const __nv_bfloat16* __restrict__ dl,
    float* __restrict__ outp)
{
    extern __shared__ unsigned sm[];
    unsigned* As = sm;
    unsigned* Hs = sm + 64*ASTR2;
    unsigned* Bs = Hs + 64*HSTR;

    const int tid  = threadIdx.x;
    const int lane = tid & 31;
    const int lr   = lane >> 2;
    const int lc   = lane & 3;
    const int w    = tid >> 5;
    const int wm   = w >> 2;
    const int wn   = w & 3;
    const int m0   = blockIdx.x * 64;

    {
        const uint4* src = (const uint4*)(A + (size_t)m0 * 128);
        #pragma unroll
        for (int s = 0; s < 4; s++) {
            int slot = tid + 256*s;
            int row = slot >> 4, c4 = slot & 15;
            *(uint4*)&As[row*ASTR2 + c4*4] = src[row*16 + c4];
        }
    }

    const unsigned bs_base = (unsigned)__cvta_generic_to_shared(Bs);
    const unsigned BSB = 128*BSTR2*4;

    #define BISSUE(Wt, rowoff, Kw, ktoff, buf) { \
        _Pragma("unroll") \
        for (int s_ = 0; s_ < 2; s_++) { \
            int slot_ = tid + 256*s_; \
            int rw_ = slot_ >> 2, c_ = slot_ & 3; \
            cp16(bs_base + (buf)*BSB + (rw_*BSTR2 + c_*4)*4, \
                 (Wt) + (size_t)((rowoff) + rw_)*(Kw) + (ktoff) + c_*8); \
        } \
        CP_COMMIT; }

    const int a_row = wm*32 + lr;
    float acc[2][4][4];

    // fc1: 16 stages = 4 chunks x 4 k-steps
    BISSUE(W1t, 0, 128, 0, 0);
    for (int st = 0; st < 16; st++) {
        if ((st & 3) == 0) {
            #pragma unroll
            for (int i = 0; i < 2; i++)
                #pragma unroll
                for (int j = 0; j < 4; j++)
                    #pragma unroll
                    for (int c = 0; c < 4; c++) acc[i][j][c] = 0.f;
        }
        if (st + 1 < 16) { BISSUE(W1t, ((st+1) >> 2)*128, 128, ((st+1) & 3)*32, (st+1) & 1); CP_WAIT1; }
        else             { CP_WAIT0; }
        __syncthreads();
        {
            const unsigned* bs = Bs + (st & 1)*128*BSTR2;
            const int koff = (st & 3)*16;
            #pragma unroll
            for (int kk2 = 0; kk2 < 16; kk2 += 8) {
                unsigned afr[2][4];
                #pragma unroll
                for (int i = 0; i < 2; i++) {
                    int base = (a_row + i*16)*ASTR2 + koff + kk2 + lc;
                    afr[i][0] = As[base];
                    afr[i][1] = As[base + 8*ASTR2];
                    afr[i][2] = As[base + 4];
                    afr[i][3] = As[base + 8*ASTR2 + 4];
                }
                #pragma unroll
                for (int j = 0; j < 4; j++) {
                    unsigned bfr[2];
                    int bb = (wn*32 + j*8 + lr)*BSTR2 + kk2 + lc;
                    bfr[0] = bs[bb];
                    bfr[1] = bs[bb + 4];
                    #pragma unroll
                    for (int i = 0; i < 2; i++)
                        mma_bf16(acc[i][j], afr[i], bfr);
                }
            }
        }
        if ((st & 3) == 3) {
            int ch = st >> 2;
            #pragma unroll
            for (int i = 0; i < 2; i++) {
                #pragma unroll
                for (int half = 0; half < 2; half++) {
                    int row = a_row + i*16 + half*8;
                    #pragma unroll
                    for (int j = 0; j < 4; j++) {
                        int n = wn*32 + j*8 + 2*lc;
                        float v0 = acc[i][j][half*2 + 0] + b1[ch*128 + n];
                        float v1 = acc[i][j][half*2 + 1] + b1[ch*128 + n + 1];
                        v0 = 0.5f*v0*(1.0f + erff(v0*0.70710678118654752f));
                        v1 = 0.5f*v1*(1.0f + erff(v1*0.70710678118654752f));
                        Hs[row*HSTR + ch*64 + wn*16 + j*4 + lc] = packbf(v0, v1);
                    }
                }
            }
        }
        __syncthreads();
    }

    // fc2: 16 k-stages of 32 over K=512
    {
        #pragma unroll
        for (int i = 0; i < 2; i++)
            #pragma unroll
            for (int j = 0; j < 4; j++)
                #pragma unroll
                for (int c = 0; c < 4; c++) acc[i][j][c] = 0.f;
    }
    BISSUE(W2t, 0, 512, 0, 0);
    for (int st = 0; st < 16; st++) {
        if (st + 1 < 16) { BISSUE(W2t, 0, 512, (st+1)*32, (st+1) & 1); CP_WAIT1; }
        else             { CP_WAIT0; }
        __syncthreads();
        {
            const unsigned* bs = Bs + (st & 1)*128*BSTR2;
            const int koff = st*16;
            #pragma unroll
            for (int kk2 = 0; kk2 < 16; kk2 += 8) {
                unsigned afr[2][4];
                #pragma unroll
                for (int i = 0; i < 2; i++) {
                    int base = (a_row + i*16)*HSTR + koff + kk2 + lc;
                    afr[i][0] = Hs[base];
                    afr[i][1] = Hs[base + 8*HSTR];
                    afr[i][2] = Hs[base + 4];
                    afr[i][3] = Hs[base + 8*HSTR + 4];
                }
                #pragma unroll
                for (int j = 0; j < 4; j++) {
                    unsigned bfr[2];
                    int bb = (wn*32 + j*8 + lr)*BSTR2 + kk2 + lc;
                    bfr[0] = bs[bb];
                    bfr[1] = bs[bb + 4];
                    #pragma unroll
                    for (int i = 0; i < 2; i++)
                        mma_bf16(acc[i][j], afr[i], bfr);
                }
            }
        }
        __syncthreads();
    }

    // final epilogue: residuals + perm scatter
    #pragma unroll
    for (int i = 0; i < 2; i++) {
        #pragma unroll
        for (int half = 0; half < 2; half++) {
            int m = m0 + a_row + i*16 + half*8;
            size_t dstrow = (size_t)perm_m(m) * 128;
            const float* hsrow = hs + dstrow;
            const __nv_bfloat16* drow = dl + (size_t)m * 128;
            #pragma unroll
            for (int j = 0; j < 4; j++) {
                int n = wn*32 + j*8 + 2*lc;
                __nv_bfloat162 db = *(const __nv_bfloat162*)&drow[n];
                float v0 = acc[i][j][half*2 + 0] + b2[n]   + hsrow[n]   + __bfloat162float(db.x);
                float v1 = acc[i][j][half*2 + 1] + b2[n+1] + hsrow[n+1] + __bfloat162float(db.y);
                *(float2*)&outp[dstrow + n] = make_float2(v0, v1);
            }
        }
    }
    #undef BISSUE
}

// ---------------- windowed attention: one block per WINDOW, 4 heads --------
// 256 threads = 8 warps = (head 0..3) x (key-half 0..1). Full-row coalesced
// Q/K/V loads shared across heads; per-warp math identical to prior version.
// Dynamic smem layout (uints):
//  Qs 64*68 | Ks 64*68 | Vt 4*32*36 | Ps 4*64*36 | rpb 900f | lab 64 | redm 512f | redsum 512f
#define ATT_QS   0
#define ATT_KS   4352
#define ATT_VT   8704
#define ATT_PS   13312
#define ATT_RPB  22528
#define ATT_LAB  23428
#define ATT_RM   23492
#define ATT_RS   24004
#define ATT_SMEM (24516*4)

__global__ void __launch_bounds__(256, 2) attn_kernel(
    const __nv_bfloat16* __restrict__ q, const __nv_bfloat16* __restrict__ k,
    const __nv_bfloat16* __restrict__ v, const float* __restrict__ rpb,
    __nv_bfloat16* __restrict__ out)
{
    extern __shared__ unsigned sm[];
    unsigned* Qs    = sm + ATT_QS;
    unsigned* Ks    = sm + ATT_KS;
    unsigned* VtAll = sm + ATT_VT;
    unsigned* PsAll = sm + ATT_PS;
    float*    rpb_s = (float*)(sm + ATT_RPB);
    int*      lab_s = (int*)(sm + ATT_LAB);
    float*    redm  = (float*)(sm + ATT_RM);
    float*    redsm = (float*)(sm + ATT_RS);

    const int win  = blockIdx.x;
    const int tid  = threadIdx.x;
    const int lane = tid & 31;
    const int lr   = lane >> 2;
    const int lc   = lane & 3;
    const int wid  = tid >> 5;
    const int head = wid >> 1;
    const int w    = wid & 1;
    const int wloc = win & 1023;
    const int wh = wloc >> 5, ww = wloc & 31;

    for (int idx = tid; idx < 900; idx += 256) rpb_s[idx] = rpb[idx];
    if (tid < 64) lab_s[tid] = 3*region(wh*8 + (tid >> 3)) + region(ww*8 + (tid & 7));

    // full-row coalesced loads; V transposed per head into Vt
    {
        const __nv_bfloat16* qb_ = q + (size_t)win*64*128;
        const __nv_bfloat16* kb_ = k + (size_t)win*64*128;
        const __nv_bfloat16* vb_ = v + (size_t)win*64*128;
        unsigned short* vtb = (unsigned short*)VtAll;
        #pragma unroll
        for (int i = 0; i < 4; i++) {
            int slot = tid + 256*i;           // 0..1023
            int row = slot >> 4, c4 = slot & 15;
            size_t off = (size_t)row*128 + c4*8;
            uint4 qq = *(const uint4*)(qb_ + off);
            uint4 kk = *(const uint4*)(kb_ + off);
            uint4 vv = *(const uint4*)(vb_ + off);
            *(uint4*)&Qs[row*68 + c4*4] = qq;
            *(uint4*)&Ks[row*68 + c4*4] = kk;
            unsigned vals[4] = {vv.x, vv.y, vv.z, vv.w};
            int h_ = c4 >> 2;                 // head of this 8-channel chunk
            int nbase = (c4 & 3)*8;           // within-head channel base
            unsigned short* vh = vtb + h_*2304;   // 1152 uints per head
            #pragma unroll
            for (int dd = 0; dd < 8; dd++) {
                int n = nbase + dd;
                vh[(n*36 + (row >> 1))*2 + (row & 1)] =
                    (unsigned short)(vals[dd >> 1] >> ((dd & 1)*16));
            }
        }
    }
    __syncthreads();

    unsigned* Ps = PsAll + head*2304;
    unsigned* Vt = VtAll + head*1152;
    float* redm_h = redm  + head*128;
    float* reds_h = redsm + head*128;
    const int hq = head*16;                   // pair-col offset in Qs/Ks

    // ---- S = Q @ K^T (bf16): warp covers key-cols [32w, 32w+32) ----
    float s[4][4][4];
    #pragma unroll
    for (int i = 0; i < 4; i++)
        #pragma unroll
        for (int j = 0; j < 4; j++)
            #pragma unroll
            for (int c = 0; c < 4; c++) s[i][j][c] = 0.f;

    const int nb0 = w*32;
    #pragma unroll
    for (int kk2 = 0; kk2 < 16; kk2 += 8) {
        unsigned afr[4][4], bfr[4][2];
        #pragma unroll
        for (int i = 0; i < 4; i++) {
            int base = (i*16 + lr)*68 + hq + kk2 + lc;
            afr[i][0] = Qs[base];
            afr[i][1] = Qs[base + 8*68];
            afr[i][2] = Qs[base + 4];
            afr[i][3] = Qs[base + 8*68 + 4];
        }
        #pragma unroll
        for (int j = 0; j < 4; j++) {
            int nn = nb0 + j*8 + lr;
            bfr[j][0] = Ks[nn*68 + hq + kk2 + lc];
            bfr[j][1] = Ks[nn*68 + hq + kk2 + lc + 4];
        }
        #pragma unroll
        for (int i = 0; i < 4; i++)
            #pragma unroll
            for (int j = 0; j < 4; j++)
                mma_bf16(s[i][j], afr[i], bfr[j]);
    }

    // ---- in-register bias + mask + row-max (partial per warp) ----
    #pragma unroll
    for (int i = 0; i < 4; i++) {
        #pragma unroll
        for (int half = 0; half < 2; half++) {
            int r = i*16 + lr + half*8;
            int labr = lab_s[r];
            int ti = r >> 3, tj = r & 7;
            float m_ = -1e30f;
            #pragma unroll
            for (int j = 0; j < 4; j++) {
                #pragma unroll
                for (int e = 0; e < 2; e++) {
                    int c = nb0 + j*8 + 2*lc + e;
                    int ki = c >> 3, kj = c & 7;
                    float val = s[i][j][half*2 + e]
                              + rpb_s[((ti - ki + 7)*15 + (tj - kj + 7))*4 + head];
                    if (lab_s[c] != labr) val -= 100.f;
                    s[i][j][half*2 + e] = val;
                    m_ = fmaxf(m_, val);
                }
            }
            m_ = fmaxf(m_, __shfl_xor_sync(0xffffffffu, m_, 1));
            m_ = fmaxf(m_, __shfl_xor_sync(0xffffffffu, m_, 2));
            if (lc == 0) redm_h[r*2 + w] = m_;
        }
    }
    __syncthreads();

    // ---- exp + row-sum (partial) + pack P bf16 ----
    #pragma unroll
    for (int i = 0; i < 4; i++) {
        #pragma unroll
        for (int half = 0; half < 2; half++) {
            int r = i*16 + lr + half*8;
            float mx = fmaxf(redm_h[r*2], redm_h[r*2 + 1]);
            float sum = 0.f;
            #pragma unroll
            for (int j = 0; j < 4; j++) {
                float e0 = __expf(s[i][j][half*2 + 0] - mx);
                float e1 = __expf(s[i][j][half*2 + 1] - mx);
                sum += e0 + e1;
                Ps[r*36 + 16*w + j*4 + lc] = packbf(e0, e1);
            }
            sum += __shfl_xor_sync(0xffffffffu, sum, 1);
            sum += __shfl_xor_sync(0xffffffffu, sum, 2);
            if (lc == 0) reds_h[r*2 + w] = sum;
        }
    }
    __syncthreads();

    // ---- O partial = P[:, 32w:) @ V[32w:, :] (bf16 mma) ----
    float o[4][4][4];
    #pragma unroll
    for (int i = 0; i < 4; i++)
        #pragma unroll
        for (int j = 0; j < 4; j++)
            #pragma unroll
            for (int c = 0; c < 4; c++) o[i][j][c] = 0.f;

    const int woff = 16*w;
    #pragma unroll
    for (int kb = 0; kb < 2; kb++) {
        unsigned afr[4][4], bfr[4][2];
        #pragma unroll
        for (int i = 0; i < 4; i++) {
            int base = (i*16 + lr)*36 + woff + kb*8 + lc;
            afr[i][0] = Ps[base];
            afr[i][1] = Ps[base + 8*36];
            afr[i][2] = Ps[base + 4];
            afr[i][3] = Ps[base + 8*36 + 4];
        }
        #pragma unroll
        for (int j = 0; j < 4; j++) {
            int base = (j*8 + lr)*36 + woff + kb*8 + lc;
            bfr[j][0] = Vt[base];
            bfr[j][1] = Vt[base + 4];
        }
        #pragma unroll
        for (int i = 0; i < 4; i++)
            #pragma unroll
            for (int j = 0; j < 4; j++)
                mma_bf16(o[i][j], afr[i], bfr[j]);
    }
    __syncthreads();

    float* Osum = (float*)Ps;   // [64][34] fp32, per head
    if (w == 1) {
        #pragma unroll
        for (int i = 0; i < 4; i++)
            #pragma unroll
            for (int j = 0; j < 4; j++) {
                int r0 = i*16 + lr;
                int n  = j*8 + 2*lc;
                *(float2*)&Osum[r0*34 + n]     = make_float2(o[i][j][0], o[i][j][1]);
                *(float2*)&Osum[(r0+8)*34 + n] = make_float2(o[i][j][2], o[i][j][3]);
            }
    }
    __syncthreads();
    if (w == 0) {
        #pragma unroll
        for (int i = 0; i < 4; i++) {
            #pragma unroll
            for (int half = 0; half < 2; half++) {
                int r = i*16 + lr + half*8;
                float inv = 1.f / (reds_h[r*2] + reds_h[r*2 + 1]);
                size_t ob = (size_t)win*64*128 + (size_t)r*128 + head*32;
                #pragma unroll
                for (int j = 0; j < 4; j++) {
                    int n = j*8 + 2*lc;
                    float v0 = (o[i][j][half*2 + 0] + Osum[r*34 + n])     * inv;
                    float v1 = (o[i][j][half*2 + 1] + Osum[r*34 + n + 1]) * inv;
                    *(unsigned*)&out[ob + n] = packbf(v0, v1);
                }
            }
        }
    }
}

// ---------------------------------------------------------------------------
extern "C" void kernel_launch(void* const* d_in, const int* in_sizes, int n_in,
                              void* d_out, int out_size)
{
    const float* hs   = (const float*)d_in[0];
    const float* l1s  = (const float*)d_in[1];
    const float* l1b  = (const float*)d_in[2];
    const float* qw   = (const float*)d_in[3];
    const float* qb   = (const float*)d_in[4];
    const float* kw   = (const float*)d_in[5];
    const float* kb   = (const float*)d_in[6];
    const float* vw   = (const float*)d_in[7];
    const float* vb   = (const float*)d_in[8];
    const float* pw   = (const float*)d_in[9];
    const float* pb   = (const float*)d_in[10];
    const float* rpb  = (const float*)d_in[11];
    const float* l2s  = (const float*)d_in[12];
    const float* l2b  = (const float*)d_in[13];
    const float* f1w  = (const float*)d_in[14];
    const float* f1b  = (const float*)d_in[15];
    const float* f2w  = (const float*)d_in[16];
    const float* f2b  = (const float*)d_in[17];
    float* outp = (float*)d_out;

    __nv_bfloat16 *xw, *qx, *kx, *vx, *ao, *dl, *l2, *wt;
    cudaGetSymbolAddress((void**)&xw,   g_xw);
    cudaGetSymbolAddress((void**)&qx,   g_q);
    cudaGetSymbolAddress((void**)&kx,   g_k);
    cudaGetSymbolAddress((void**)&vx,   g_v);
    cudaGetSymbolAddress((void**)&ao,   g_ao);
    cudaGetSymbolAddress((void**)&dl,   g_dl);
    cudaGetSymbolAddress((void**)&l2,   g_l2);
    cudaGetSymbolAddress((void**)&wt,   g_wt);

    __nv_bfloat16* qt  = wt;
    __nv_bfloat16* kt  = wt + 16384;
    __nv_bfloat16* vt  = wt + 32768;
    __nv_bfloat16* pt  = wt + 49152;
    __nv_bfloat16* f1t = wt + 65536;
    __nv_bfloat16* f2t = wt + 131072;

    cudaFuncSetAttribute(gemm_tc,     cudaFuncAttributeMaxDynamicSharedMemorySize, GEMM_SMEM);
    cudaFuncSetAttribute(mlp_fused,   cudaFuncAttributeMaxDynamicSharedMemorySize, MLP_SMEM);
    cudaFuncSetAttribute(attn_kernel, cudaFuncAttributeMaxDynamicSharedMemorySize, ATT_SMEM);

    const float qscale = 0.17677669529663687f;  // 1/sqrt(32)

    // 0. fused weight prep
    prep_all<<<768, 256>>>(qw, kw, vw, pw, f1w, f2w, wt);
    // 1. LN1 + shift + window partition (bf16 out)
    ln_kernel<<<MTOK/8, 256>>>(hs, l1s, l1b, xw, 1);
    // 2. fused QKV projections
    gemm_tc<<<dim3(3, MTOK/BM), 256, GEMM_SMEM>>>(xw, qt, qb, qx, kt, kb, kx, vt, vb, vx,
                                       128, 128, qscale, 0, nullptr, nullptr, nullptr, nullptr);
    // 3. windowed attention: one block per window, 4 heads
    attn_kernel<<<4096, 256, ATT_SMEM>>>(qx, kx, vx, rpb, ao);
    // 4. proj -> delta bf16; LN2(hs[perm]+delta) -> l2
    gemm_tc<<<dim3(1, MTOK/BM), 256, GEMM_SMEM>>>(ao, pt, pb, dl, nullptr, nullptr, nullptr,
                                       nullptr, nullptr, nullptr,
                                       128, 128, 1.0f, 1, hs, l2, l2s, l2b);
    // 5+6. fused MLP: fc1 + GELU + fc2 + residuals -> out[perm]
    mlp_fused<<<MTOK/64, 256, MLP_SMEM>>>(l2, f1t, f1b, f2t, f2b, hs, dl, outp);
}

// round 10
// speedup vs baseline: 1.0795x; 1.0795x over previous
#include <cuda_runtime.h>
#include <cuda_bf16.h>
#include <math.h>

#define MTOK 262144   // B*H*W = 4*256*256
#define CDIM 128
#define HID  512

// ---------------- scratch (device globals: allocation-free) ----------------
__device__ __nv_bfloat16 g_xw[(size_t)MTOK*CDIM];  // LN1 + shift + window partition
__device__ __nv_bfloat16 g_q [(size_t)MTOK*CDIM];
__device__ __nv_bfloat16 g_k [(size_t)MTOK*CDIM];
__device__ __nv_bfloat16 g_v [(size_t)MTOK*CDIM];
__device__ __nv_bfloat16 g_ao[(size_t)MTOK*CDIM];  // attention output (window order)
__device__ __nv_bfloat16 g_wt[196608];             // transposed bf16 weights [N][K]

__device__ __forceinline__ int region(int a) { return a < 248 ? 0 : (a < 252 ? 1 : 2); }

__device__ __forceinline__ void mma_bf16(float c[4], const unsigned a[4], const unsigned b[2]) {
    asm volatile("mma.sync.aligned.m16n8k16.row.col.f32.bf16.bf16.f32 "
        "{%0,%1,%2,%3}, {%4,%5,%6,%7}, {%8,%9}, {%0,%1,%2,%3};\n"
        : "+f"(c[0]), "+f"(c[1]), "+f"(c[2]), "+f"(c[3])
        : "r"(a[0]), "r"(a[1]), "r"(a[2]), "r"(a[3]), "r"(b[0]), "r"(b[1]));
}
__device__ __forceinline__ void cp16(unsigned dst, const void* src) {
    asm volatile("cp.async.cg.shared.global [%0], [%1], 16;\n" :: "r"(dst), "l"(src));
}
#define CP_COMMIT asm volatile("cp.async.commit_group;\n" ::: "memory")
#define CP_WAIT1  asm volatile("cp.async.wait_group 1;\n" ::: "memory")
#define CP_WAIT0  asm volatile("cp.async.wait_group 0;\n" ::: "memory")

// window-order index m -> original token index (window reverse + roll(+4,+4))
__device__ __forceinline__ int perm_m(int m) {
    int b = m >> 16, w = (m >> 6) & 1023, t = m & 63;
    int wh = w >> 5, ww = w & 31, ti = t >> 3, tj = t & 7;
    int r = (wh*8 + ti + 4) & 255;
    int c = (ww*8 + tj + 4) & 255;
    return (b << 16) | (r << 8) | c;
}
__device__ __forceinline__ unsigned packbf(float a, float b) {
    __nv_bfloat162 t = __floats2bfloat162_rn(a, b);
    return *(unsigned*)&t;
}
__device__ __forceinline__ float gelu_f(float v) {
    return 0.5f*v*(1.0f + erff(v*0.70710678118654752f));
}

// ---------------- fused weight prep: all six matrices in one launch --------
__global__ void prep_all(const float* __restrict__ qw, const float* __restrict__ kw,
                         const float* __restrict__ vw, const float* __restrict__ pw,
                         const float* __restrict__ f1w, const float* __restrict__ f2w,
                         __nv_bfloat16* __restrict__ wt)
{
    int idx = blockIdx.x * 256 + threadIdx.x;     // 0..196607
    float v;
    if (idx < 65536) {
        int seg = idx >> 14;
        int rel = idx & 16383;
        int n = rel >> 7, k = rel & 127;
        const float* src = seg == 0 ? qw : (seg == 1 ? kw : (seg == 2 ? vw : pw));
        v = src[k*128 + n];
    } else if (idx < 131072) {
        int rel = idx - 65536;            // f1t [512][128] <- f1w [128][512]
        int n = rel >> 7, k = rel & 127;
        v = f1w[k*512 + n];
    } else {
        int rel = idx - 131072;           // f2t [128][512] <- f2w [512][128]
        int n = rel >> 9, k = rel & 511;
        v = f2w[k*128 + n];
    }
    wt[idx] = __float2bfloat16(v);
}

// ---------------- LayerNorm (fused with shift+window gather), bf16 out -----
__global__ void ln_kernel(const float* __restrict__ in, const float* __restrict__ gamma,
                          const float* __restrict__ beta, __nv_bfloat16* __restrict__ out,
                          int gather)
{
    int token = blockIdx.x * 8 + (threadIdx.x >> 5);
    int lane  = threadIdx.x & 31;
    int src = gather ? perm_m(token) : token;
    float4 xv = ((const float4*)in)[(size_t)src*32 + lane];
    float s  = xv.x + xv.y + xv.z + xv.w;
    float sq = xv.x*xv.x + xv.y*xv.y + xv.z*xv.z + xv.w*xv.w;
    #pragma unroll
    for (int o = 16; o; o >>= 1) {
        s  += __shfl_xor_sync(0xffffffffu, s,  o);
        sq += __shfl_xor_sync(0xffffffffu, sq, o);
    }
    float mean = s * (1.f/128.f);
    float var  = sq * (1.f/128.f) - mean*mean;
    float rstd = rsqrtf(var + 1e-5f);
    float4 g  = ((const float4*)gamma)[lane];
    float4 bt = ((const float4*)beta)[lane];
    uint2 pk;
    pk.x = packbf((xv.x - mean)*rstd*g.x + bt.x, (xv.y - mean)*rstd*g.y + bt.y);
    pk.y = packbf((xv.z - mean)*rstd*g.z + bt.z, (xv.w - mean)*rstd*g.w + bt.w);
    ((uint2*)out)[(size_t)token*32 + lane] = pk;
}

// ---------------- bf16 tensor-core GEMM (fused QKV only) -------------------
#define BM 128
#define BN 128
#define BK 32
#define ASTR 20
#define BSTR 20
#define NST 3
#define SA_W (BM*ASTR)
#define SB_W (BN*BSTR)
#define GEMM_SMEM ((NST*(SA_W + SB_W))*4)

__global__ void __launch_bounds__(256, 2) gemm_tc(
    const __nv_bfloat16* __restrict__ A,
    const __nv_bfloat16* __restrict__ W0, const float* __restrict__ B0, __nv_bfloat16* __restrict__ C0,
    const __nv_bfloat16* __restrict__ W1, const float* __restrict__ B1, __nv_bfloat16* __restrict__ C1,
    const __nv_bfloat16* __restrict__ W2, const float* __restrict__ B2, __nv_bfloat16* __restrict__ C2,
    float scale)
{
    extern __shared__ unsigned smem[];
    unsigned* AsB = smem;
    unsigned* BsB = smem + NST*SA_W;

    const int tid  = threadIdx.x;
    const int lane = tid & 31;
    const int lr   = lane >> 2;
    const int lc   = lane & 3;
    const int w    = tid >> 5;
    const int wm   = w >> 2;
    const int wn   = w & 3;
    const int m0   = blockIdx.y * BM;
    const int K = 128;

    int s = blockIdx.x;
    const __nv_bfloat16* Bw = s == 0 ? W0 : (s == 1 ? W1 : W2);
    const float* bias       = s == 0 ? B0 : (s == 1 ? B1 : B2);
    __nv_bfloat16* Cout     = s == 0 ? C0 : (s == 1 ? C1 : C2);
    float sc                = s == 0 ? scale : 1.0f;

    const int grow = tid >> 2;
    const int gc8  = (tid & 3) << 3;

    const __nv_bfloat16* Ap0 = A  + (size_t)(m0 + grow) * K + gc8;
    const __nv_bfloat16* Ap1 = Ap0 + (size_t)64 * K;
    const __nv_bfloat16* Bp0 = Bw + (size_t)grow * K + gc8;
    const __nv_bfloat16* Bp1 = Bp0 + (size_t)64 * K;

    const unsigned a_base = (unsigned)__cvta_generic_to_shared(AsB);
    const unsigned b_base = (unsigned)__cvta_generic_to_shared(BsB);
    const unsigned a_s0 = a_base + (grow*ASTR + (tid & 3)*4)*4;
    const unsigned a_s1 = a_base + ((grow+64)*ASTR + (tid & 3)*4)*4;
    const unsigned b_s0 = b_base + (grow*BSTR + (tid & 3)*4)*4;
    const unsigned b_s1 = b_base + ((grow+64)*BSTR + (tid & 3)*4)*4;
    const unsigned SAB = SA_W*4, SBB = SB_W*4;

    const int stages = K >> 5;   // 4

    #define ISSUE(t, buf) { \
        int kt_ = (t) << 5; \
        cp16(a_s0 + (buf)*SAB, Ap0 + kt_); \
        cp16(a_s1 + (buf)*SAB, Ap1 + kt_); \
        cp16(b_s0 + (buf)*SBB, Bp0 + kt_); \
        cp16(b_s1 + (buf)*SBB, Bp1 + kt_); \
        CP_COMMIT; }

    ISSUE(0, 0);
    ISSUE(1, 1);
    CP_WAIT1;
    __syncthreads();

    float acc[4][4][4];
    #pragma unroll
    for (int i = 0; i < 4; i++)
        #pragma unroll
        for (int j = 0; j < 4; j++)
            #pragma unroll
            for (int c = 0; c < 4; c++) acc[i][j][c] = 0.f;

    const int a_off = (wm*64 + lr)*ASTR + lc;
    const int b_off = (wn*32 + lr)*BSTR + lc;

    for (int t = 0; t < stages; t++) {
        const unsigned* as = AsB + (t % NST)*SA_W;
        const unsigned* bs = BsB + (t % NST)*SB_W;
        #pragma unroll
        for (int kk2 = 0; kk2 < 16; kk2 += 8) {
            unsigned afr[4][4];
            #pragma unroll
            for (int i = 0; i < 4; i++) {
                int base = a_off + i*16*ASTR + kk2;
                afr[i][0] = as[base];
                afr[i][1] = as[base + 8*ASTR];
                afr[i][2] = as[base + 4];
                afr[i][3] = as[base + 8*ASTR + 4];
            }
            #pragma unroll
            for (int j = 0; j < 4; j++) {
                unsigned bfr[2];
                int bb = b_off + j*8*BSTR + kk2;
                bfr[0] = bs[bb];
                bfr[1] = bs[bb + 4];
                #pragma unroll
                for (int i = 0; i < 4; i++)
                    mma_bf16(acc[i][j], afr[i], bfr);
            }
        }
        if (t + 2 < stages) {
            ISSUE(t + 2, (t + 2) % NST);
            CP_WAIT1;
            __syncthreads();
        } else if (t + 1 < stages) {
            CP_WAIT0;
            __syncthreads();
        }
    }
    #undef ISSUE

    #pragma unroll
    for (int i = 0; i < 4; i++) {
        #pragma unroll
        for (int half = 0; half < 2; half++) {
            int m = m0 + wm*64 + i*16 + lr + half*8;
            size_t dstrow = (size_t)m * 128;
            #pragma unroll
            for (int j = 0; j < 4; j++) {
                int n = wn*32 + j*8 + 2*lc;
                float v0 = (acc[i][j][half*2 + 0] + bias[n]) * sc;
                float v1 = (acc[i][j][half*2 + 1] + bias[n+1]) * sc;
                *(unsigned*)&Cout[dstrow + n] = packbf(v0, v1);
            }
        }
    }
}

// ---------------- windowed attention (R8 design: block per (win,head)) -----
__global__ void __launch_bounds__(64) attn_kernel(
    const __nv_bfloat16* __restrict__ q, const __nv_bfloat16* __restrict__ k,
    const __nv_bfloat16* __restrict__ v, const float* __restrict__ rpb,
    __nv_bfloat16* __restrict__ out)
{
    __shared__ unsigned Qs[64*20];
    __shared__ unsigned Ks[64*20];
    __shared__ unsigned Vt[32*36];
    __shared__ unsigned Ps[64*36];
    __shared__ float    rpb_s[225];
    __shared__ int      lab_s[64];
    __shared__ float    redm[128];
    __shared__ float    redsum[128];

    const int win  = blockIdx.x >> 2;
    const int head = blockIdx.x & 3;
    const int tid  = threadIdx.x;
    const int lane = tid & 31;
    const int lr   = lane >> 2;
    const int lc   = lane & 3;
    const int w    = tid >> 5;
    const int wloc = win & 1023;
    const int wh = wloc >> 5, ww = wloc & 31;

    for (int idx = tid; idx < 225; idx += 64) rpb_s[idx] = rpb[idx*4 + head];
    lab_s[tid] = 3*region(wh*8 + (tid >> 3)) + region(ww*8 + (tid & 7));

    {
        const __nv_bfloat16* qb_ = q + (size_t)win*64*128 + head*32;
        const __nv_bfloat16* kb_ = k + (size_t)win*64*128 + head*32;
        const __nv_bfloat16* vb_ = v + (size_t)win*64*128 + head*32;
        unsigned short* vtb = (unsigned short*)Vt;
        #pragma unroll
        for (int i = 0; i < 4; i++) {
            int idx = tid + 64*i;
            int tok = idx >> 2, ch = idx & 3;
            size_t off = (size_t)tok*128 + ch*8;
            uint4 qq = *(const uint4*)(qb_ + off);
            uint4 kk = *(const uint4*)(kb_ + off);
            uint4 vv = *(const uint4*)(vb_ + off);
            *(uint4*)&Qs[tok*20 + ch*4] = qq;
            *(uint4*)&Ks[tok*20 + ch*4] = kk;
            unsigned vals[4] = {vv.x, vv.y, vv.z, vv.w};
            #pragma unroll
            for (int d = 0; d < 8; d++) {
                int n = ch*8 + d;
                vtb[(n*36 + (tok >> 1))*2 + (tok & 1)] =
                    (unsigned short)(vals[d >> 1] >> ((d & 1)*16));
            }
        }
    }
    __syncthreads();

    float s[4][4][4];
    #pragma unroll
    for (int i = 0; i < 4; i++)
        #pragma unroll
        for (int j = 0; j < 4; j++)
            #pragma unroll
            for (int c = 0; c < 4; c++) s[i][j][c] = 0.f;

    const int nb0 = w*32;
    #pragma unroll
    for (int kk2 = 0; kk2 < 16; kk2 += 8) {
        unsigned afr[4][4], bfr[4][2];
        #pragma unroll
        for (int i = 0; i < 4; i++) {
            int base = (i*16 + lr)*20 + kk2 + lc;
            afr[i][0] = Qs[base];
            afr[i][1] = Qs[base + 8*20];
            afr[i][2] = Qs[base + 4];
            afr[i][3] = Qs[base + 8*20 + 4];
        }
        #pragma unroll
        for (int j = 0; j < 4; j++) {
            int nn = nb0 + j*8 + lr;
            bfr[j][0] = Ks[nn*20 + kk2 + lc];
            bfr[j][1] = Ks[nn*20 + kk2 + lc + 4];
        }
        #pragma unroll
        for (int i = 0; i < 4; i++)
            #pragma unroll
            for (int j = 0; j < 4; j++)
                mma_bf16(s[i][j], afr[i], bfr[j]);
    }

    #pragma unroll
    for (int i = 0; i < 4; i++) {
        #pragma unroll
        for (int half = 0; half < 2; half++) {
            int r = i*16 + lr + half*8;
            int labr = lab_s[r];
            int ti = r >> 3, tj = r & 7;
            float m_ = -1e30f;
            #pragma unroll
            for (int j = 0; j < 4; j++) {
                #pragma unroll
                for (int e = 0; e < 2; e++) {
                    int c = nb0 + j*8 + 2*lc + e;
                    int ki = c >> 3, kj = c & 7;
                    float val = s[i][j][half*2 + e]
                              + rpb_s[(ti - ki + 7)*15 + (tj - kj + 7)];
                    if (lab_s[c] != labr) val -= 100.f;
                    s[i][j][half*2 + e] = val;
                    m_ = fmaxf(m_, val);
                }
            }
            m_ = fmaxf(m_, __shfl_xor_sync(0xffffffffu, m_, 1));
            m_ = fmaxf(m_, __shfl_xor_sync(0xffffffffu, m_, 2));
            if (lc == 0) redm[r*2 + w] = m_;
        }
    }
    __syncthreads();

    #pragma unroll
    for (int i = 0; i < 4; i++) {
        #pragma unroll
        for (int half = 0; half < 2; half++) {
            int r = i*16 + lr + half*8;
            float mx = fmaxf(redm[r*2], redm[r*2 + 1]);
            float sum = 0.f;
            #pragma unroll
            for (int j = 0; j < 4; j++) {
                float e0 = __expf(s[i][j][half*2 + 0] - mx);
                float e1 = __expf(s[i][j][half*2 + 1] - mx);
                sum += e0 + e1;
                Ps[r*36 + 16*w + j*4 + lc] = packbf(e0, e1);
            }
            sum += __shfl_xor_sync(0xffffffffu, sum, 1);
            sum += __shfl_xor_sync(0xffffffffu, sum, 2);
            if (lc == 0) redsum[r*2 + w] = sum;
        }
    }
    __syncthreads();

    float o[4][4][4];
    #pragma unroll
    for (int i = 0; i < 4; i++)
        #pragma unroll
        for (int j = 0; j < 4; j++)
            #pragma unroll
            for (int c = 0; c < 4; c++) o[i][j][c] = 0.f;

    const int woff = 16*w;
    #pragma unroll
    for (int kb = 0; kb < 2; kb++) {
        unsigned afr[4][4], bfr[4][2];
        #pragma unroll
        for (int i = 0; i < 4; i++) {
            int base = (i*16 + lr)*36 + woff + kb*8 + lc;
            afr[i][0] = Ps[base];
            afr[i][1] = Ps[base + 8*36];
            afr[i][2] = Ps[base + 4];
            afr[i][3] = Ps[base + 8*36 + 4];
        }
        #pragma unroll
        for (int j = 0; j < 4; j++) {
            int base = (j*8 + lr)*36 + woff + kb*8 + lc;
            bfr[j][0] = Vt[base];
            bfr[j][1] = Vt[base + 4];
        }
        #pragma unroll
        for (int i = 0; i < 4; i++)
            #pragma unroll
            for (int j = 0; j < 4; j++)
                mma_bf16(o[i][j], afr[i], bfr[j]);
    }
    __syncthreads();

    float* Osum = (float*)Ps;
    if (w == 1) {
        #pragma unroll
        for (int i = 0; i < 4; i++)
            #pragma unroll
            for (int j = 0; j < 4; j++) {
                int r0 = i*16 + lr;
                int n  = j*8 + 2*lc;
                *(float2*)&Osum[r0*34 + n]     = make_float2(o[i][j][0], o[i][j][1]);
                *(float2*)&Osum[(r0+8)*34 + n] = make_float2(o[i][j][2], o[i][j][3]);
            }
    }
    __syncthreads();
    if (w == 0) {
        #pragma unroll
        for (int i = 0; i < 4; i++) {
            #pragma unroll
            for (int half = 0; half < 2; half++) {
                int r = i*16 + lr + half*8;
                float inv = 1.f / (redsum[r*2] + redsum[r*2 + 1]);
                size_t ob = (size_t)win*64*128 + (size_t)r*128 + head*32;
                #pragma unroll
                for (int j = 0; j < 4; j++) {
                    int n = j*8 + 2*lc;
                    float v0 = (o[i][j][half*2 + 0] + Osum[r*34 + n])     * inv;
                    float v1 = (o[i][j][half*2 + 1] + Osum[r*34 + n + 1]) * inv;
                    *(unsigned*)&out[ob + n] = packbf(v0, v1);
                }
            }
        }
    }
}

// ---------------- fused tail: proj + shortcut + LN2 + fc1+GELU + fc2 + out -
// One block = 64 tokens, 256 threads = 8 warps (wm 0..1 x wn 0..3).
// 36 double-buffered weight stages: 4 proj + 4x(4 fc1 + 4 fc2-partial).
// x = hs[perm] + proj + pb held in smem fp32; h per-chunk in smem (no HID buf).
// smem (uints): As 64*68 | L2s 64*68 | Hc 64*68 | Xs(f32) 64*132 | Bs 2*128*20 | red 2*256
#define T_AS 0
#define T_L2 4352
#define T_HC 8704
#define T_XS 13056
#define T_BS 21504
#define T_RS 26624
#define T_RQ 26880
#define TAIL_SMEM (27136*4)

__global__ void __launch_bounds__(256, 2) tail_fused(
    const __nv_bfloat16* __restrict__ ao,
    const __nv_bfloat16* __restrict__ pt,  const float* __restrict__ pb,
    const __nv_bfloat16* __restrict__ f1t, const float* __restrict__ b1,
    const __nv_bfloat16* __restrict__ f2t, const float* __restrict__ b2,
    const float* __restrict__ hs,
    const float* __restrict__ gamma, const float* __restrict__ beta,
    float* __restrict__ outp)
{
    extern __shared__ unsigned sm[];
    unsigned* As  = sm + T_AS;
    unsigned* L2s = sm + T_L2;
    unsigned* Hc  = sm + T_HC;
    float*    Xs  = (float*)(sm + T_XS);
    unsigned* Bs  = sm + T_BS;
    float*    red_s = (float*)(sm + T_RS);
    float*    red_q = (float*)(sm + T_RQ);

    const int tid  = threadIdx.x;
    const int lane = tid & 31;
    const int lr   = lane >> 2;
    const int lc   = lane & 3;
    const int w    = tid >> 5;
    const int wm   = w >> 2;
    const int wn   = w & 3;
    const int m0   = blockIdx.x * 64;
    const int a_row = wm*32 + lr;

    const unsigned bs_base = (unsigned)__cvta_generic_to_shared(Bs);
    const unsigned as_base = (unsigned)__cvta_generic_to_shared(As);
    const unsigned xs_base = (unsigned)__cvta_generic_to_shared(Xs);
    const unsigned BSB = 128*20*4;

    #define ISSUE_ST(st_, buf_) { \
        int stq_ = (st_); \
        const __nv_bfloat16* W_; int ro_, Kw_, ko_; \
        if (stq_ < 4) { W_ = pt; ro_ = 0; Kw_ = 128; ko_ = stq_*32; } \
        else { int t_ = stq_-4; int ch_ = t_>>3; int s2_ = t_&3; \
               if (((t_>>2)&1) == 0) { W_ = f1t; ro_ = ch_*128; Kw_ = 128; ko_ = s2_*32; } \
               else                  { W_ = f2t; ro_ = 0; Kw_ = 512; ko_ = ch_*128 + s2_*32; } } \
        _Pragma("unroll") \
        for (int s_ = 0; s_ < 2; s_++) { \
            int slot_ = tid + 256*s_; \
            int rw_ = slot_ >> 2, c_ = slot_ & 3; \
            cp16(bs_base + (buf_)*BSB + (rw_*20 + c_*4)*4, \
                 W_ + (size_t)(ro_ + rw_)*Kw_ + ko_ + c_*8); \
        } CP_COMMIT; }

    // phase A: stage ao tile + hs[perm] rows, lumped with weight stage 0
    {
        const __nv_bfloat16* aop = ao + (size_t)m0 * 128;
        #pragma unroll
        for (int s_ = 0; s_ < 4; s_++) {
            int slot = tid + 256*s_;
            int row = slot >> 4, c4 = slot & 15;
            cp16(as_base + (row*68 + c4*4)*4, aop + (size_t)row*128 + c4*8);
        }
        #pragma unroll
        for (int s_ = 0; s_ < 8; s_++) {
            int slot = tid + 256*s_;
            int row = slot >> 5, q4 = slot & 31;
            cp16(xs_base + (row*132 + q4*4)*4,
                 hs + (size_t)perm_m(m0 + row)*128 + q4*4);
        }
        ISSUE_ST(0, 0);   // commits A loads + B stage0 as one group
    }

    float acc1[2][4][4], acc2[2][4][4];
    #pragma unroll
    for (int i = 0; i < 2; i++)
        #pragma unroll
        for (int j = 0; j < 4; j++)
            #pragma unroll
            for (int c = 0; c < 4; c++) acc2[i][j][c] = 0.f;

    #define STAGE_MMA(SRC, KOFF, ACC) { \
        const unsigned* bsl = Bs + (st & 1)*128*20; \
        _Pragma("unroll") \
        for (int kk2 = 0; kk2 < 16; kk2 += 8) { \
            unsigned afr[2][4]; \
            _Pragma("unroll") \
            for (int i = 0; i < 2; i++) { \
                int base = (a_row + i*16)*68 + (KOFF) + kk2 + lc; \
                afr[i][0] = SRC[base]; \
                afr[i][1] = SRC[base + 8*68]; \
                afr[i][2] = SRC[base + 4]; \
                afr[i][3] = SRC[base + 8*68 + 4]; \
            } \
            _Pragma("unroll") \
            for (int j = 0; j < 4; j++) { \
                unsigned bfr[2]; \
                int bb = (wn*32 + j*8 + lr)*20 + kk2 + lc; \
                bfr[0] = bsl[bb]; \
                bfr[1] = bsl[bb + 4]; \
                _Pragma("unroll") \
                for (int i = 0; i < 2; i++) \
                    mma_bf16(ACC[i][j], afr[i], bfr); \
            } } }

    for (int st = 0; st < 36; st++) {
        if (st + 1 < 36) { ISSUE_ST(st + 1, (st + 1) & 1); CP_WAIT1; }
        else             { CP_WAIT0; }
        __syncthreads();

        if (st < 4) {
            if (st == 0) {
                #pragma unroll
                for (int i = 0; i < 2; i++)
                    #pragma unroll
                    for (int j = 0; j < 4; j++)
                        #pragma unroll
                        for (int c = 0; c < 4; c++) acc1[i][j][c] = 0.f;
            }
            STAGE_MMA(As, st*16, acc1);
            if (st == 3) {
                // proj epilogue: x = acc + pb + hs (in Xs); LN2 stats
                #pragma unroll
                for (int i = 0; i < 2; i++) {
                    #pragma unroll
                    for (int half = 0; half < 2; half++) {
                        int row = a_row + i*16 + half*8;
                        float s = 0.f, q = 0.f;
                        #pragma unroll
                        for (int j = 0; j < 4; j++) {
                            int n = wn*32 + j*8 + 2*lc;
                            float x0 = acc1[i][j][half*2 + 0] + pb[n]   + Xs[row*132 + n];
                            float x1 = acc1[i][j][half*2 + 1] + pb[n+1] + Xs[row*132 + n + 1];
                            *(float2*)&Xs[row*132 + n] = make_float2(x0, x1);
                            s += x0 + x1;
                            q += x0*x0 + x1*x1;
                        }
                        s += __shfl_xor_sync(0xffffffffu, s, 1);
                        s += __shfl_xor_sync(0xffffffffu, s, 2);
                        q += __shfl_xor_sync(0xffffffffu, q, 1);
                        q += __shfl_xor_sync(0xffffffffu, q, 2);
                        if (lc == 0) { red_s[row*4 + wn] = s; red_q[row*4 + wn] = q; }
                    }
                }
                __syncthreads();
                #pragma unroll
                for (int i = 0; i < 2; i++) {
                    #pragma unroll
                    for (int half = 0; half < 2; half++) {
                        int row = a_row + i*16 + half*8;
                        float s = red_s[row*4+0] + red_s[row*4+1] + red_s[row*4+2] + red_s[row*4+3];
                        float q = red_q[row*4+0] + red_q[row*4+1] + red_q[row*4+2] + red_q[row*4+3];
                        float mu = s * (1.f/128.f);
                        float var = q * (1.f/128.f) - mu*mu;
                        float rstd = rsqrtf(var + 1e-5f);
                        #pragma unroll
                        for (int j = 0; j < 4; j++) {
                            int n = wn*32 + j*8 + 2*lc;
                            float x0 = Xs[row*132 + n];
                            float x1 = Xs[row*132 + n + 1];
                            float l0 = (x0 - mu)*rstd*gamma[n]   + beta[n];
                            float l1 = (x1 - mu)*rstd*gamma[n+1] + beta[n+1];
                            L2s[row*68 + wn*16 + j*4 + lc] = packbf(l0, l1);
                        }
                    }
                }
            }
        } else {
            int t = st - 4;
            int ch = t >> 3, s2 = t & 3, ph = (t >> 2) & 1;
            if (ph == 0) {
                if (s2 == 0) {
                    #pragma unroll
                    for (int i = 0; i < 2; i++)
                        #pragma unroll
                        for (int j = 0; j < 4; j++)
                            #pragma unroll
                            for (int c = 0; c < 4; c++) acc1[i][j][c] = 0.f;
                }
                STAGE_MMA(L2s, s2*16, acc1);
                if (s2 == 3) {
                    // fc1 chunk epilogue: gelu -> Hc
                    #pragma unroll
                    for (int i = 0; i < 2; i++) {
                        #pragma unroll
                        for (int half = 0; half < 2; half++) {
                            int row = a_row + i*16 + half*8;
                            #pragma unroll
                            for (int j = 0; j < 4; j++) {
                                int n = wn*32 + j*8 + 2*lc;
                                float v0 = gelu_f(acc1[i][j][half*2 + 0] + b1[ch*128 + n]);
                                float v1 = gelu_f(acc1[i][j][half*2 + 1] + b1[ch*128 + n + 1]);
                                Hc[row*68 + wn*16 + j*4 + lc] = packbf(v0, v1);
                            }
                        }
                    }
                }
            } else {
                STAGE_MMA(Hc, s2*16, acc2);
            }
        }
        __syncthreads();
    }
    #undef STAGE_MMA
    #undef ISSUE_ST

    // final epilogue: out[perm(m)] = x + mlp_out + b2
    #pragma unroll
    for (int i = 0; i < 2; i++) {
        #pragma unroll
        for (int half = 0; half < 2; half++) {
            int rloc = a_row + i*16 + half*8;
            int m = m0 + rloc;
            size_t dstrow = (size_t)perm_m(m) * 128;
            #pragma unroll
            for (int j = 0; j < 4; j++) {
                int n = wn*32 + j*8 + 2*lc;
                float v0 = acc2[i][j][half*2 + 0] + b2[n]   + Xs[rloc*132 + n];
                float v1 = acc2[i][j][half*2 + 1] + b2[n+1] + Xs[rloc*132 + n + 1];
                *(float2*)&outp[dstrow + n] = make_float2(v0, v1);
            }
        }
    }
}

// ---------------------------------------------------------------------------
extern "C" void kernel_launch(void* const* d_in, const int* in_sizes, int n_in,
                              void* d_out, int out_size)
{
    const float* hs   = (const float*)d_in[0];
    const float* l1s  = (const float*)d_in[1];
    const float* l1b  = (const float*)d_in[2];
    const float* qw   = (const float*)d_in[3];
    const float* qb   = (const float*)d_in[4];
    const float* kw   = (const float*)d_in[5];
    const float* kb   = (const float*)d_in[6];
    const float* vw   = (const float*)d_in[7];
    const float* vb   = (const float*)d_in[8];
    const float* pw   = (const float*)d_in[9];
    const float* pb   = (const float*)d_in[10];
    const float* rpb  = (const float*)d_in[11];
    const float* l2s  = (const float*)d_in[12];
    const float* l2b  = (const float*)d_in[13];
    const float* f1w  = (const float*)d_in[14];
    const float* f1b  = (const float*)d_in[15];
    const float* f2w  = (const float*)d_in[16];
    const float* f2b  = (const float*)d_in[17];
    float* outp = (float*)d_out;

    __nv_bfloat16 *xw, *qx, *kx, *vx, *ao, *wt;
    cudaGetSymbolAddress((void**)&xw, g_xw);
    cudaGetSymbolAddress((void**)&qx, g_q);
    cudaGetSymbolAddress((void**)&kx, g_k);
    cudaGetSymbolAddress((void**)&vx, g_v);
    cudaGetSymbolAddress((void**)&ao, g_ao);
    cudaGetSymbolAddress((void**)&wt, g_wt);

    __nv_bfloat16* qt  = wt;
    __nv_bfloat16* kt  = wt + 16384;
    __nv_bfloat16* vt  = wt + 32768;
    __nv_bfloat16* pt  = wt + 49152;
    __nv_bfloat16* f1t = wt + 65536;   // [512][128]
    __nv_bfloat16* f2t = wt + 131072;  // [128][512]

    cudaFuncSetAttribute(gemm_tc,    cudaFuncAttributeMaxDynamicSharedMemorySize, GEMM_SMEM);
    cudaFuncSetAttribute(tail_fused, cudaFuncAttributeMaxDynamicSharedMemorySize, TAIL_SMEM);

    const float qscale = 0.17677669529663687f;  // 1/sqrt(32)

    // 0. fused weight prep
    prep_all<<<768, 256>>>(qw, kw, vw, pw, f1w, f2w, wt);
    // 1. LN1 + shift + window partition (bf16 out)
    ln_kernel<<<MTOK/8, 256>>>(hs, l1s, l1b, xw, 1);
    // 2. fused QKV projections
    gemm_tc<<<dim3(3, MTOK/BM), 256, GEMM_SMEM>>>(xw, qt, qb, qx, kt, kb, kx, vt, vb, vx, qscale);
    // 3. windowed attention (R8 design)
    attn_kernel<<<4096*4, 64>>>(qx, kx, vx, rpb, ao);
    // 4. fused tail: proj + shortcut + LN2 + fc1 + GELU + fc2 + residual -> out[perm]
    tail_fused<<<MTOK/64, 256, TAIL_SMEM>>>(ao, pt, pb, f1t, f1b, f2t, f2b,
                                            hs, l2s, l2b, outp);
}

// round 11
// speedup vs baseline: 1.2227x; 1.1326x over previous
#include <cuda_runtime.h>
#include <cuda_bf16.h>
#include <math.h>

#define MTOK 262144   // B*H*W = 4*256*256
#define CDIM 128
#define HID  512

// ---------------- scratch (device globals: allocation-free) ----------------
__device__ __nv_bfloat16 g_xw[(size_t)MTOK*CDIM];  // LN1 + shift + window partition
__device__ __nv_bfloat16 g_ao[(size_t)MTOK*CDIM];  // attention output (window order)
__device__ __nv_bfloat16 g_wt[196608];             // transposed bf16 weights [N][K]

__device__ __forceinline__ int region(int a) { return a < 248 ? 0 : (a < 252 ? 1 : 2); }

__device__ __forceinline__ void mma_bf16(float c[4], const unsigned a[4], const unsigned b[2]) {
    asm volatile("mma.sync.aligned.m16n8k16.row.col.f32.bf16.bf16.f32 "
        "{%0,%1,%2,%3}, {%4,%5,%6,%7}, {%8,%9}, {%0,%1,%2,%3};\n"
        : "+f"(c[0]), "+f"(c[1]), "+f"(c[2]), "+f"(c[3])
        : "r"(a[0]), "r"(a[1]), "r"(a[2]), "r"(a[3]), "r"(b[0]), "r"(b[1]));
}
__device__ __forceinline__ void cp16(unsigned dst, const void* src) {
    asm volatile("cp.async.cg.shared.global [%0], [%1], 16;\n" :: "r"(dst), "l"(src));
}
#define CP_COMMIT asm volatile("cp.async.commit_group;\n" ::: "memory")
#define CP_WAIT1  asm volatile("cp.async.wait_group 1;\n" ::: "memory")
#define CP_WAIT0  asm volatile("cp.async.wait_group 0;\n" ::: "memory")

// window-order index m -> original token index (window reverse + roll(+4,+4))
__device__ __forceinline__ int perm_m(int m) {
    int b = m >> 16, w = (m >> 6) & 1023, t = m & 63;
    int wh = w >> 5, ww = w & 31, ti = t >> 3, tj = t & 7;
    int r = (wh*8 + ti + 4) & 255;
    int c = (ww*8 + tj + 4) & 255;
    return (b << 16) | (r << 8) | c;
}
__device__ __forceinline__ unsigned packbf(float a, float b) {
    __nv_bfloat162 t = __floats2bfloat162_rn(a, b);
    return *(unsigned*)&t;
}
__device__ __forceinline__ unsigned short bf16u(float a) {
    __nv_bfloat16 t = __float2bfloat16(a);
    return *(unsigned short*)&t;
}
__device__ __forceinline__ float gelu_f(float v) {
    return 0.5f*v*(1.0f + erff(v*0.70710678118654752f));
}

// ---------------- fused weight prep: all six matrices in one launch --------
__global__ void prep_all(const float* __restrict__ qw, const float* __restrict__ kw,
                         const float* __restrict__ vw, const float* __restrict__ pw,
                         const float* __restrict__ f1w, const float* __restrict__ f2w,
                         __nv_bfloat16* __restrict__ wt)
{
    int idx = blockIdx.x * 256 + threadIdx.x;     // 0..196607
    float v;
    if (idx < 65536) {
        int seg = idx >> 14;
        int rel = idx & 16383;
        int n = rel >> 7, k = rel & 127;
        const float* src = seg == 0 ? qw : (seg == 1 ? kw : (seg == 2 ? vw : pw));
        v = src[k*128 + n];
    } else if (idx < 131072) {
        int rel = idx - 65536;            // f1t [512][128] <- f1w [128][512]
        int n = rel >> 7, k = rel & 127;
        v = f1w[k*512 + n];
    } else {
        int rel = idx - 131072;           // f2t [128][512] <- f2w [512][128]
        int n = rel >> 9, k = rel & 511;
        v = f2w[k*128 + n];
    }
    wt[idx] = __float2bfloat16(v);
}

// ---------------- LayerNorm (fused with shift+window gather), bf16 out -----
__global__ void ln_kernel(const float* __restrict__ in, const float* __restrict__ gamma,
                          const float* __restrict__ beta, __nv_bfloat16* __restrict__ out,
                          int gather)
{
    int token = blockIdx.x * 8 + (threadIdx.x >> 5);
    int lane  = threadIdx.x & 31;
    int src = gather ? perm_m(token) : token;
    float4 xv = ((const float4*)in)[(size_t)src*32 + lane];
    float s  = xv.x + xv.y + xv.z + xv.w;
    float sq = xv.x*xv.x + xv.y*xv.y + xv.z*xv.z + xv.w*xv.w;
    #pragma unroll
    for (int o = 16; o; o >>= 1) {
        s  += __shfl_xor_sync(0xffffffffu, s,  o);
        sq += __shfl_xor_sync(0xffffffffu, sq, o);
    }
    float mean = s * (1.f/128.f);
    float var  = sq * (1.f/128.f) - mean*mean;
    float rstd = rsqrtf(var + 1e-5f);
    float4 g  = ((const float4*)gamma)[lane];
    float4 bt = ((const float4*)beta)[lane];
    uint2 pk;
    pk.x = packbf((xv.x - mean)*rstd*g.x + bt.x, (xv.y - mean)*rstd*g.y + bt.y);
    pk.y = packbf((xv.z - mean)*rstd*g.z + bt.z, (xv.w - mean)*rstd*g.w + bt.w);
    ((uint2*)out)[(size_t)token*32 + lane] = pk;
}

// ---------------- fused QKV + windowed attention ---------------------------
// One block per WINDOW, 256 threads = 8 warps.
// Phase 1 (QKV): A = xw tile 64x128 (smem); Wqkv = wt[0:384][128] streamed in
//   12 double-buffered k-stages; epilogues write Qs/Ks (pair layout) and Vt
//   (per-head transposed) directly from accumulators.
// Phase 2 (attn): warp = (head, key-half). S mma + in-register softmax
//   (cross-warp max/sum via smem). PV: full-K per warp (rows split) -> no
//   partial-sum exchange; both warps write output.
// smem (uints): [Xw 64*68 | Wb 2*128*20] (aliased later by Ps 4*64*36)
//               | Qs 64*68 | Ks 64*68 | Vt 4*32*36 | rpb 900 | lab 64
//               | redm 512 | redsum 512
#define AQ_XW   0
#define AQ_WB   4352
#define AQ_PS   0
#define AQ_QS   9472
#define AQ_KS   13824
#define AQ_VT   18176
#define AQ_RPB  22784
#define AQ_LAB  23684
#define AQ_RM   23748
#define AQ_RS   24260
#define AQ_SMEM (24772*4)

__global__ void __launch_bounds__(256, 2) qkv_attn(
    const __nv_bfloat16* __restrict__ xw,
    const __nv_bfloat16* __restrict__ wqkv,   // [384][128] = qt|kt|vt
    const float* __restrict__ qb, const float* __restrict__ kb, const float* __restrict__ vb,
    const float* __restrict__ rpb, float scale,
    __nv_bfloat16* __restrict__ out)
{
    extern __shared__ unsigned sm[];
    unsigned* Xw = sm + AQ_XW;
    unsigned* Wb = sm + AQ_WB;
    unsigned* Qs = sm + AQ_QS;
    unsigned* Ks = sm + AQ_KS;
    float*    rpb_s = (float*)(sm + AQ_RPB);
    int*      lab_s = (int*)(sm + AQ_LAB);
    float*    redm  = (float*)(sm + AQ_RM);
    float*    redsm = (float*)(sm + AQ_RS);
    unsigned short* vtb = (unsigned short*)(sm + AQ_VT);

    const int win  = blockIdx.x;
    const int tid  = threadIdx.x;
    const int lane = tid & 31;
    const int lr   = lane >> 2;
    const int lc   = lane & 3;
    const int wid  = tid >> 5;
    const int wloc = win & 1023;
    const int wh = wloc >> 5, ww = wloc & 31;

    // stage rpb + labels (plain loads, overlap with cp.async below)
    for (int idx = tid; idx < 900; idx += 256) rpb_s[idx] = rpb[idx];
    if (tid < 64) lab_s[tid] = 3*region(wh*8 + (tid >> 3)) + region(ww*8 + (tid & 7));

    const unsigned xw_base = (unsigned)__cvta_generic_to_shared(Xw);
    const unsigned wb_base = (unsigned)__cvta_generic_to_shared(Wb);
    const unsigned WBB = 128*20*4;

    #define WISSUE(st_, buf_) { \
        int c_ = (st_) >> 2, ko_ = ((st_) & 3)*32; \
        _Pragma("unroll") \
        for (int s_ = 0; s_ < 2; s_++) { \
            int slot_ = tid + 256*s_; \
            int rw_ = slot_ >> 2, cc_ = slot_ & 3; \
            cp16(wb_base + (buf_)*WBB + (rw_*20 + cc_*4)*4, \
                 wqkv + (size_t)(c_*128 + rw_)*128 + ko_ + cc_*8); \
        } CP_COMMIT; }

    // prologue: xw tile + weight stage 0 in one group, stage 1 in a second
    {
        const __nv_bfloat16* xp = xw + (size_t)win*64*128;
        #pragma unroll
        for (int s_ = 0; s_ < 4; s_++) {
            int slot = tid + 256*s_;
            int row = slot >> 4, c4 = slot & 15;
            cp16(xw_base + (row*68 + c4*4)*4, xp + (size_t)row*128 + c4*8);
        }
        WISSUE(0, 0);
    }
    WISSUE(1, 1);

    // QKV phase: 12 stages (3 chunks x 4 k-steps). Warp (wm, wn): 32x32 tile.
    const int wm = wid >> 2;      // 0..1
    const int wn = wid & 3;       // 0..3
    const int a_row = wm*32 + lr;
    float acc[2][4][4];

    CP_WAIT1;
    __syncthreads();

    for (int st = 0; st < 12; st++) {
        if (st + 1 < 12) { WISSUE(st + 1, (st + 1) & 1); CP_WAIT1; }
        else             { CP_WAIT0; }
        if (st > 0) __syncthreads();   // weights buf ready / prev reads done

        if ((st & 3) == 0) {
            #pragma unroll
            for (int i = 0; i < 2; i++)
                #pragma unroll
                for (int j = 0; j < 4; j++)
                    #pragma unroll
                    for (int c = 0; c < 4; c++) acc[i][j][c] = 0.f;
        }
        {
            const unsigned* bsl = Wb + (st & 1)*128*20;
            const int koff = (st & 3)*16;
            #pragma unroll
            for (int kk2 = 0; kk2 < 16; kk2 += 8) {
                unsigned afr[2][4];
                #pragma unroll
                for (int i = 0; i < 2; i++) {
                    int base = (a_row + i*16)*68 + koff + kk2 + lc;
                    afr[i][0] = Xw[base];
                    afr[i][1] = Xw[base + 8*68];
                    afr[i][2] = Xw[base + 4];
                    afr[i][3] = Xw[base + 8*68 + 4];
                }
                #pragma unroll
                for (int j = 0; j < 4; j++) {
                    unsigned bfr[2];
                    int bb = (wn*32 + j*8 + lr)*20 + kk2 + lc;
                    bfr[0] = bsl[bb];
                    bfr[1] = bsl[bb + 4];
                    #pragma unroll
                    for (int i = 0; i < 2; i++)
                        mma_bf16(acc[i][j], afr[i], bfr);
                }
            }
        }
        if ((st & 3) == 3) {
            int chunk = st >> 2;   // 0=Q, 1=K, 2=V
            #pragma unroll
            for (int i = 0; i < 2; i++) {
                #pragma unroll
                for (int half = 0; half < 2; half++) {
                    int row = a_row + i*16 + half*8;
                    #pragma unroll
                    for (int j = 0; j < 4; j++) {
                        int n = wn*32 + j*8 + 2*lc;
                        if (chunk == 0) {
                            float v0 = (acc[i][j][half*2 + 0] + qb[n]) * scale;
                            float v1 = (acc[i][j][half*2 + 1] + qb[n+1]) * scale;
                            Qs[row*68 + wn*16 + j*4 + lc] = packbf(v0, v1);
                        } else if (chunk == 1) {
                            float v0 = acc[i][j][half*2 + 0] + kb[n];
                            float v1 = acc[i][j][half*2 + 1] + kb[n+1];
                            Ks[row*68 + wn*16 + j*4 + lc] = packbf(v0, v1);
                        } else {
                            float v0 = acc[i][j][half*2 + 0] + vb[n];
                            float v1 = acc[i][j][half*2 + 1] + vb[n+1];
                            int h0 = n >> 5,  nl0 = n & 31;
                            int h1 = (n+1) >> 5, nl1 = (n+1) & 31;
                            vtb[h0*2304 + nl0*72 + row] = bf16u(v0);
                            vtb[h1*2304 + nl1*72 + row] = bf16u(v1);
                        }
                    }
                }
            }
        }
        __syncthreads();
    }
    #undef WISSUE

    // ---------------- attention phase: warp = (head, key-half) -------------
    const int head = wid >> 1;
    const int w    = wid & 1;
    unsigned* Ps   = sm + AQ_PS + head*2304;      // aliases Xw/Wb (dead now)
    unsigned* Vt   = sm + AQ_VT + head*1152;
    float* redm_h  = redm  + head*128;
    float* reds_h  = redsm + head*128;
    const int hq   = head*16;

    // S = Q @ K^T : warp covers key-cols [32w, 32w+32)
    float s[4][4][4];
    #pragma unroll
    for (int i = 0; i < 4; i++)
        #pragma unroll
        for (int j = 0; j < 4; j++)
            #pragma unroll
            for (int c = 0; c < 4; c++) s[i][j][c] = 0.f;

    const int nb0 = w*32;
    #pragma unroll
    for (int kk2 = 0; kk2 < 16; kk2 += 8) {
        unsigned afr[4][4], bfr[4][2];
        #pragma unroll
        for (int i = 0; i < 4; i++) {
            int base = (i*16 + lr)*68 + hq + kk2 + lc;
            afr[i][0] = Qs[base];
            afr[i][1] = Qs[base + 8*68];
            afr[i][2] = Qs[base + 4];
            afr[i][3] = Qs[base + 8*68 + 4];
        }
        #pragma unroll
        for (int j = 0; j < 4; j++) {
            int nn = nb0 + j*8 + lr;
            bfr[j][0] = Ks[nn*68 + hq + kk2 + lc];
            bfr[j][1] = Ks[nn*68 + hq + kk2 + lc + 4];
        }
        #pragma unroll
        for (int i = 0; i < 4; i++)
            #pragma unroll
            for (int j = 0; j < 4; j++)
                mma_bf16(s[i][j], afr[i], bfr[j]);
    }

    // in-register bias + mask + partial row-max
    #pragma unroll
    for (int i = 0; i < 4; i++) {
        #pragma unroll
        for (int half = 0; half < 2; half++) {
            int r = i*16 + lr + half*8;
            int labr = lab_s[r];
            int ti = r >> 3, tj = r & 7;
            float m_ = -1e30f;
            #pragma unroll
            for (int j = 0; j < 4; j++) {
                #pragma unroll
                for (int e = 0; e < 2; e++) {
                    int c = nb0 + j*8 + 2*lc + e;
                    int ki = c >> 3, kj = c & 7;
                    float val = s[i][j][half*2 + e]
                              + rpb_s[((ti - ki + 7)*15 + (tj - kj + 7))*4 + head];
                    if (lab_s[c] != labr) val -= 100.f;
                    s[i][j][half*2 + e] = val;
                    m_ = fmaxf(m_, val);
                }
            }
            m_ = fmaxf(m_, __shfl_xor_sync(0xffffffffu, m_, 1));
            m_ = fmaxf(m_, __shfl_xor_sync(0xffffffffu, m_, 2));
            if (lc == 0) redm_h[r*2 + w] = m_;
        }
    }
    __syncthreads();

    // exp + partial row-sum + pack P bf16 (Ps aliases dead Xw/Wb region)
    #pragma unroll
    for (int i = 0; i < 4; i++) {
        #pragma unroll
        for (int half = 0; half < 2; half++) {
            int r = i*16 + lr + half*8;
            float mx = fmaxf(redm_h[r*2], redm_h[r*2 + 1]);
            float sum = 0.f;
            #pragma unroll
            for (int j = 0; j < 4; j++) {
                float e0 = __expf(s[i][j][half*2 + 0] - mx);
                float e1 = __expf(s[i][j][half*2 + 1] - mx);
                sum += e0 + e1;
                Ps[r*36 + 16*w + j*4 + lc] = packbf(e0, e1);
            }
            sum += __shfl_xor_sync(0xffffffffu, sum, 1);
            sum += __shfl_xor_sync(0xffffffffu, sum, 2);
            if (lc == 0) reds_h[r*2 + w] = sum;
        }
    }
    __syncthreads();

    // O = P @ V : full K per warp; warp covers query rows [32w, 32w+32)
    float o[2][4][4];
    #pragma unroll
    for (int i = 0; i < 2; i++)
        #pragma unroll
        for (int j = 0; j < 4; j++)
            #pragma unroll
            for (int c = 0; c < 4; c++) o[i][j][c] = 0.f;

    const int mb = w*32;
    #pragma unroll
    for (int kb = 0; kb < 4; kb++) {
        unsigned afr[2][4], bfr[4][2];
        #pragma unroll
        for (int i = 0; i < 2; i++) {
            int base = (mb + i*16 + lr)*36 + kb*8 + lc;
            afr[i][0] = Ps[base];
            afr[i][1] = Ps[base + 8*36];
            afr[i][2] = Ps[base + 4];
            afr[i][3] = Ps[base + 8*36 + 4];
        }
        #pragma unroll
        for (int j = 0; j < 4; j++) {
            int base = (j*8 + lr)*36 + kb*8 + lc;
            bfr[j][0] = Vt[base];
            bfr[j][1] = Vt[base + 4];
        }
        #pragma unroll
        for (int i = 0; i < 2; i++)
            #pragma unroll
            for (int j = 0; j < 4; j++)
                mma_bf16(o[i][j], afr[i], bfr[j]);
    }

    // write output (both warps; no partial-sum exchange needed)
    #pragma unroll
    for (int i = 0; i < 2; i++) {
        #pragma unroll
        for (int half = 0; half < 2; half++) {
            int r = mb + i*16 + lr + half*8;
            float inv = 1.f / (reds_h[r*2] + reds_h[r*2 + 1]);
            size_t ob = (size_t)win*64*128 + (size_t)r*128 + head*32;
            #pragma unroll
            for (int j = 0; j < 4; j++) {
                int n = j*8 + 2*lc;
                float v0 = o[i][j][half*2 + 0] * inv;
                float v1 = o[i][j][half*2 + 1] * inv;
                *(unsigned*)&out[ob + n] = packbf(v0, v1);
            }
        }
    }
}

// ---------------- fused tail: proj + shortcut + LN2 + fc1+GELU + fc2 + out -
#define T_AS 0
#define T_L2 4352
#define T_HC 8704
#define T_XS 13056
#define T_BS 21504
#define T_RS 26624
#define T_RQ 26880
#define TAIL_SMEM (27136*4)

__global__ void __launch_bounds__(256, 2) tail_fused(
    const __nv_bfloat16* __restrict__ ao,
    const __nv_bfloat16* __restrict__ pt,  const float* __restrict__ pb,
    const __nv_bfloat16* __restrict__ f1t, const float* __restrict__ b1,
    const __nv_bfloat16* __restrict__ f2t, const float* __restrict__ b2,
    const float* __restrict__ hs,
    const float* __restrict__ gamma, const float* __restrict__ beta,
    float* __restrict__ outp)
{
    extern __shared__ unsigned sm[];
    unsigned* As  = sm + T_AS;
    unsigned* L2s = sm + T_L2;
    unsigned* Hc  = sm + T_HC;
    float*    Xs  = (float*)(sm + T_XS);
    unsigned* Bs  = sm + T_BS;
    float*    red_s = (float*)(sm + T_RS);
    float*    red_q = (float*)(sm + T_RQ);

    const int tid  = threadIdx.x;
    const int lane = tid & 31;
    const int lr   = lane >> 2;
    const int lc   = lane & 3;
    const int w    = tid >> 5;
    const int wm   = w >> 2;
    const int wn   = w & 3;
    const int m0   = blockIdx.x * 64;
    const int a_row = wm*32 + lr;

    const unsigned bs_base = (unsigned)__cvta_generic_to_shared(Bs);
    const unsigned as_base = (unsigned)__cvta_generic_to_shared(As);
    const unsigned xs_base = (unsigned)__cvta_generic_to_shared(Xs);
    const unsigned BSB = 128*20*4;

    #define ISSUE_ST(st_, buf_) { \
        int stq_ = (st_); \
        const __nv_bfloat16* W_; int ro_, Kw_, ko_; \
        if (stq_ < 4) { W_ = pt; ro_ = 0; Kw_ = 128; ko_ = stq_*32; } \
        else { int t_ = stq_-4; int ch_ = t_>>3; int s2_ = t_&3; \
               if (((t_>>2)&1) == 0) { W_ = f1t; ro_ = ch_*128; Kw_ = 128; ko_ = s2_*32; } \
               else                  { W_ = f2t; ro_ = 0; Kw_ = 512; ko_ = ch_*128 + s2_*32; } } \
        _Pragma("unroll") \
        for (int s_ = 0; s_ < 2; s_++) { \
            int slot_ = tid + 256*s_; \
            int rw_ = slot_ >> 2, c_ = slot_ & 3; \
            cp16(bs_base + (buf_)*BSB + (rw_*20 + c_*4)*4, \
                 W_ + (size_t)(ro_ + rw_)*Kw_ + ko_ + c_*8); \
        } CP_COMMIT; }

    {
        const __nv_bfloat16* aop = ao + (size_t)m0 * 128;
        #pragma unroll
        for (int s_ = 0; s_ < 4; s_++) {
            int slot = tid + 256*s_;
            int row = slot >> 4, c4 = slot & 15;
            cp16(as_base + (row*68 + c4*4)*4, aop + (size_t)row*128 + c4*8);
        }
        #pragma unroll
        for (int s_ = 0; s_ < 8; s_++) {
            int slot = tid + 256*s_;
            int row = slot >> 5, q4 = slot & 31;
            cp16(xs_base + (row*132 + q4*4)*4,
                 hs + (size_t)perm_m(m0 + row)*128 + q4*4);
        }
        ISSUE_ST(0, 0);
    }

    float acc1[2][4][4], acc2[2][4][4];
    #pragma unroll
    for (int i = 0; i < 2; i++)
        #pragma unroll
        for (int j = 0; j < 4; j++)
            #pragma unroll
            for (int c = 0; c < 4; c++) acc2[i][j][c] = 0.f;

    #define STAGE_MMA(SRC, KOFF, ACC) { \
        const unsigned* bsl = Bs + (st & 1)*128*20; \
        _Pragma("unroll") \
        for (int kk2 = 0; kk2 < 16; kk2 += 8) { \
            unsigned afr[2][4]; \
            _Pragma("unroll") \
            for (int i = 0; i < 2; i++) { \
                int base = (a_row + i*16)*68 + (KOFF) + kk2 + lc; \
                afr[i][0] = SRC[base]; \
                afr[i][1] = SRC[base + 8*68]; \
                afr[i][2] = SRC[base + 4]; \
                afr[i][3] = SRC[base + 8*68 + 4]; \
            } \
            _Pragma("unroll") \
            for (int j = 0; j < 4; j++) { \
                unsigned bfr[2]; \
                int bb = (wn*32 + j*8 + lr)*20 + kk2 + lc; \
                bfr[0] = bsl[bb]; \
                bfr[1] = bsl[bb + 4]; \
                _Pragma("unroll") \
                for (int i = 0; i < 2; i++) \
                    mma_bf16(ACC[i][j], afr[i], bfr); \
            } } }

    for (int st = 0; st < 36; st++) {
        if (st + 1 < 36) { ISSUE_ST(st + 1, (st + 1) & 1); CP_WAIT1; }
        else             { CP_WAIT0; }
        __syncthreads();

        if (st < 4) {
            if (st == 0) {
                #pragma unroll
                for (int i = 0; i < 2; i++)
                    #pragma unroll
                    for (int j = 0; j < 4; j++)
                        #pragma unroll
                        for (int c = 0; c < 4; c++) acc1[i][j][c] = 0.f;
            }
            STAGE_MMA(As, st*16, acc1);
            if (st == 3) {
                #pragma unroll
                for (int i = 0; i < 2; i++) {
                    #pragma unroll
                    for (int half = 0; half < 2; half++) {
                        int row = a_row + i*16 + half*8;
                        float s = 0.f, q = 0.f;
                        #pragma unroll
                        for (int j = 0; j < 4; j++) {
                            int n = wn*32 + j*8 + 2*lc;
                            float x0 = acc1[i][j][half*2 + 0] + pb[n]   + Xs[row*132 + n];
                            float x1 = acc1[i][j][half*2 + 1] + pb[n+1] + Xs[row*132 + n + 1];
                            *(float2*)&Xs[row*132 + n] = make_float2(x0, x1);
                            s += x0 + x1;
                            q += x0*x0 + x1*x1;
                        }
                        s += __shfl_xor_sync(0xffffffffu, s, 1);
                        s += __shfl_xor_sync(0xffffffffu, s, 2);
                        q += __shfl_xor_sync(0xffffffffu, q, 1);
                        q += __shfl_xor_sync(0xffffffffu, q, 2);
                        if (lc == 0) { red_s[row*4 + wn] = s; red_q[row*4 + wn] = q; }
                    }
                }
                __syncthreads();
                #pragma unroll
                for (int i = 0; i < 2; i++) {
                    #pragma unroll
                    for (int half = 0; half < 2; half++) {
                        int row = a_row + i*16 + half*8;
                        float s = red_s[row*4+0] + red_s[row*4+1] + red_s[row*4+2] + red_s[row*4+3];
                        float q = red_q[row*4+0] + red_q[row*4+1] + red_q[row*4+2] + red_q[row*4+3];
                        float mu = s * (1.f/128.f);
                        float var = q * (1.f/128.f) - mu*mu;
                        float rstd = rsqrtf(var + 1e-5f);
                        #pragma unroll
                        for (int j = 0; j < 4; j++) {
                            int n = wn*32 + j*8 + 2*lc;
                            float x0 = Xs[row*132 + n];
                            float x1 = Xs[row*132 + n + 1];
                            float l0 = (x0 - mu)*rstd*gamma[n]   + beta[n];
                            float l1 = (x1 - mu)*rstd*gamma[n+1] + beta[n+1];
                            L2s[row*68 + wn*16 + j*4 + lc] = packbf(l0, l1);
                        }
                    }
                }
            }
        } else {
            int t = st - 4;
            int ch = t >> 3, s2 = t & 3, ph = (t >> 2) & 1;
            if (ph == 0) {
                if (s2 == 0) {
                    #pragma unroll
                    for (int i = 0; i < 2; i++)
                        #pragma unroll
                        for (int j = 0; j < 4; j++)
                            #pragma unroll
                            for (int c = 0; c < 4; c++) acc1[i][j][c] = 0.f;
                }
                STAGE_MMA(L2s, s2*16, acc1);
                if (s2 == 3) {
                    #pragma unroll
                    for (int i = 0; i < 2; i++) {
                        #pragma unroll
                        for (int half = 0; half < 2; half++) {
                            int row = a_row + i*16 + half*8;
                            #pragma unroll
                            for (int j = 0; j < 4; j++) {
                                int n = wn*32 + j*8 + 2*lc;
                                float v0 = gelu_f(acc1[i][j][half*2 + 0] + b1[ch*128 + n]);
                                float v1 = gelu_f(acc1[i][j][half*2 + 1] + b1[ch*128 + n + 1]);
                                Hc[row*68 + wn*16 + j*4 + lc] = packbf(v0, v1);
                            }
                        }
                    }
                }
            } else {
                STAGE_MMA(Hc, s2*16, acc2);
            }
        }
        __syncthreads();
    }
    #undef STAGE_MMA
    #undef ISSUE_ST

    #pragma unroll
    for (int i = 0; i < 2; i++) {
        #pragma unroll
        for (int half = 0; half < 2; half++) {
            int rloc = a_row + i*16 + half*8;
            int m = m0 + rloc;
            size_t dstrow = (size_t)perm_m(m) * 128;
            #pragma unroll
            for (int j = 0; j < 4; j++) {
                int n = wn*32 + j*8 + 2*lc;
                float v0 = acc2[i][j][half*2 + 0] + b2[n]   + Xs[rloc*132 + n];
                float v1 = acc2[i][j][half*2 + 1] + b2[n+1] + Xs[rloc*132 + n + 1];
                *(float2*)&outp[dstrow + n] = make_float2(v0, v1);
            }
        }
    }
}

// ---------------------------------------------------------------------------
extern "C" void kernel_launch(void* const* d_in, const int* in_sizes, int n_in,
                              void* d_out, int out_size)
{
    const float* hs   = (const float*)d_in[0];
    const float* l1s  = (const float*)d_in[1];
    const float* l1b  = (const float*)d_in[2];
    const float* qw   = (const float*)d_in[3];
    const float* qb   = (const float*)d_in[4];
    const float* kw   = (const float*)d_in[5];
    const float* kb   = (const float*)d_in[6];
    const float* vw   = (const float*)d_in[7];
    const float* vb   = (const float*)d_in[8];
    const float* pw   = (const float*)d_in[9];
    const float* pb   = (const float*)d_in[10];
    const float* rpb  = (const float*)d_in[11];
    const float* l2s  = (const float*)d_in[12];
    const float* l2b  = (const float*)d_in[13];
    const float* f1w  = (const float*)d_in[14];
    const float* f1b  = (const float*)d_in[15];
    const float* f2w  = (const float*)d_in[16];
    const float* f2b  = (const float*)d_in[17];
    float* outp = (float*)d_out;

    __nv_bfloat16 *xw, *ao, *wt;
    cudaGetSymbolAddress((void**)&xw, g_xw);
    cudaGetSymbolAddress((void**)&ao, g_ao);
    cudaGetSymbolAddress((void**)&wt, g_wt);

    __nv_bfloat16* pt  = wt + 49152;
    __nv_bfloat16* f1t = wt + 65536;   // [512][128]
    __nv_bfloat16* f2t = wt + 131072;  // [128][512]

    cudaFuncSetAttribute(qkv_attn,   cudaFuncAttributeMaxDynamicSharedMemorySize, AQ_SMEM);
    cudaFuncSetAttribute(tail_fused, cudaFuncAttributeMaxDynamicSharedMemorySize, TAIL_SMEM);

    const float qscale = 0.17677669529663687f;  // 1/sqrt(32)

    // 0. fused weight prep (qt|kt|vt contiguous at wt = Wqkv [384][128])
    prep_all<<<768, 256>>>(qw, kw, vw, pw, f1w, f2w, wt);
    // 1. LN1 + shift + window partition (bf16 out)
    ln_kernel<<<MTOK/8, 256>>>(hs, l1s, l1b, xw, 1);
    // 2. fused QKV + windowed attention (one block per window)
    qkv_attn<<<4096, 256, AQ_SMEM>>>(xw, wt, qb, kb, vb, rpb, qscale, ao);
    // 3. fused tail: proj + shortcut + LN2 + fc1 + GELU + fc2 + residual
    tail_fused<<<MTOK/64, 256, TAIL_SMEM>>>(ao, pt, pb, f1t, f1b, f2t, f2b,
                                            hs, l2s, l2b, outp);
}

// round 12
// speedup vs baseline: 1.3566x; 1.1096x over previous
#include <cuda_runtime.h>
#include <cuda_bf16.h>
#include <math.h>

#define MTOK 262144   // B*H*W = 4*256*256
#define CDIM 128
#define HID  512

// ---------------- scratch (device globals: allocation-free) ----------------
__device__ __nv_bfloat16 g_xw[(size_t)MTOK*CDIM];  // LN1 + shift + window partition
__device__ __nv_bfloat16 g_ao[(size_t)MTOK*CDIM];  // attention output (window order)
__device__ __nv_bfloat16 g_wt[49152];              // Wqkv [384][128] bf16
__device__ __nv_bfloat16 g_tb[147456];             // tail blob: 18 slabs [128][64]

__device__ __forceinline__ int region(int a) { return a < 248 ? 0 : (a < 252 ? 1 : 2); }

__device__ __forceinline__ void mma_bf16(float c[4], const unsigned a[4], const unsigned b[2]) {
    asm volatile("mma.sync.aligned.m16n8k16.row.col.f32.bf16.bf16.f32 "
        "{%0,%1,%2,%3}, {%4,%5,%6,%7}, {%8,%9}, {%0,%1,%2,%3};\n"
        : "+f"(c[0]), "+f"(c[1]), "+f"(c[2]), "+f"(c[3])
        : "r"(a[0]), "r"(a[1]), "r"(a[2]), "r"(a[3]), "r"(b[0]), "r"(b[1]));
}
__device__ __forceinline__ void cp16(unsigned dst, const void* src) {
    asm volatile("cp.async.cg.shared.global [%0], [%1], 16;\n" :: "r"(dst), "l"(src));
}
#define CP_COMMIT asm volatile("cp.async.commit_group;\n" ::: "memory")
#define CP_WAIT1  asm volatile("cp.async.wait_group 1;\n" ::: "memory")
#define CP_WAIT0  asm volatile("cp.async.wait_group 0;\n" ::: "memory")

// window-order index m -> original token index (window reverse + roll(+4,+4))
__device__ __forceinline__ int perm_m(int m) {
    int b = m >> 16, w = (m >> 6) & 1023, t = m & 63;
    int wh = w >> 5, ww = w & 31, ti = t >> 3, tj = t & 7;
    int r = (wh*8 + ti + 4) & 255;
    int c = (ww*8 + tj + 4) & 255;
    return (b << 16) | (r << 8) | c;
}
__device__ __forceinline__ unsigned packbf(float a, float b) {
    __nv_bfloat162 t = __floats2bfloat162_rn(a, b);
    return *(unsigned*)&t;
}
__device__ __forceinline__ unsigned short bf16u(float a) {
    __nv_bfloat16 t = __float2bfloat16(a);
    return *(unsigned short*)&t;
}
__device__ __forceinline__ float gelu_f(float v) {
    return 0.5f*v*(1.0f + erff(v*0.70710678118654752f));
}

// ---------------- fused weight prep ----------------------------------------
// g_wt: Wqkv [384][128] (q|k|v transposed). g_tb: 18 slabs [128][64] in tail
// consumption order: proj k0,k1 | for ch in 0..3: f1(ch) k0,k1, f2 kchunk lo,hi.
__global__ void prep_all(const float* __restrict__ qw, const float* __restrict__ kw,
                         const float* __restrict__ vw, const float* __restrict__ pw,
                         const float* __restrict__ f1w, const float* __restrict__ f2w,
                         __nv_bfloat16* __restrict__ wt, __nv_bfloat16* __restrict__ tb)
{
    int idx = blockIdx.x * 256 + threadIdx.x;     // 0..196607
    if (idx < 49152) {
        int seg = idx >> 14;                      // 0=q,1=k,2=v
        int rel = idx & 16383;
        int n = rel >> 7, k = rel & 127;
        const float* src = seg == 0 ? qw : (seg == 1 ? kw : vw);
        wt[idx] = __float2bfloat16(src[k*128 + n]);
    } else {
        int i2 = idx - 49152;                     // 0..147455
        int st = i2 >> 13;                        // slab 0..17
        int rel = i2 & 8191;
        int r = rel >> 6, c = rel & 63;
        float v;
        if (st < 2) {
            v = pw[(st*64 + c)*128 + r];
        } else {
            int t = st - 2, ch = t >> 2, s = t & 3;
            if (s < 2) v = f1w[(s*64 + c)*512 + ch*128 + r];
            else       v = f2w[(ch*128 + (s-2)*64 + c)*128 + r];
        }
        tb[i2] = __float2bfloat16(v);
    }
}

// ---------------- LayerNorm (fused with shift+window gather), bf16 out -----
__global__ void ln_kernel(const float* __restrict__ in, const float* __restrict__ gamma,
                          const float* __restrict__ beta, __nv_bfloat16* __restrict__ out,
                          int gather)
{
    int token = blockIdx.x * 8 + (threadIdx.x >> 5);
    int lane  = threadIdx.x & 31;
    int src = gather ? perm_m(token) : token;
    float4 xv = ((const float4*)in)[(size_t)src*32 + lane];
    float s  = xv.x + xv.y + xv.z + xv.w;
    float sq = xv.x*xv.x + xv.y*xv.y + xv.z*xv.z + xv.w*xv.w;
    #pragma unroll
    for (int o = 16; o; o >>= 1) {
        s  += __shfl_xor_sync(0xffffffffu, s,  o);
        sq += __shfl_xor_sync(0xffffffffu, sq, o);
    }
    float mean = s * (1.f/128.f);
    float var  = sq * (1.f/128.f) - mean*mean;
    float rstd = rsqrtf(var + 1e-5f);
    float4 g  = ((const float4*)gamma)[lane];
    float4 bt = ((const float4*)beta)[lane];
    uint2 pk;
    pk.x = packbf((xv.x - mean)*rstd*g.x + bt.x, (xv.y - mean)*rstd*g.y + bt.y);
    pk.y = packbf((xv.z - mean)*rstd*g.z + bt.z, (xv.w - mean)*rstd*g.w + bt.w);
    ((uint2*)out)[(size_t)token*32 + lane] = pk;
}

// ---------------- fused QKV + windowed attention ---------------------------
#define AQ_XW   0
#define AQ_WB   4352
#define AQ_PS   0
#define AQ_QS   9472
#define AQ_KS   13824
#define AQ_VT   18176
#define AQ_RPB  22784
#define AQ_LAB  23684
#define AQ_RM   23748
#define AQ_RS   24260
#define AQ_SMEM (24772*4)

__global__ void __launch_bounds__(256, 2) qkv_attn(
    const __nv_bfloat16* __restrict__ xw,
    const __nv_bfloat16* __restrict__ wqkv,   // [384][128]
    const float* __restrict__ qb, const float* __restrict__ kb, const float* __restrict__ vb,
    const float* __restrict__ rpb, float scale,
    __nv_bfloat16* __restrict__ out)
{
    extern __shared__ unsigned sm[];
    unsigned* Xw = sm + AQ_XW;
    unsigned* Wb = sm + AQ_WB;
    unsigned* Qs = sm + AQ_QS;
    unsigned* Ks = sm + AQ_KS;
    float*    rpb_s = (float*)(sm + AQ_RPB);
    int*      lab_s = (int*)(sm + AQ_LAB);
    float*    redm  = (float*)(sm + AQ_RM);
    float*    redsm = (float*)(sm + AQ_RS);
    unsigned short* vtb = (unsigned short*)(sm + AQ_VT);

    const int win  = blockIdx.x;
    const int tid  = threadIdx.x;
    const int lane = tid & 31;
    const int lr   = lane >> 2;
    const int lc   = lane & 3;
    const int wid  = tid >> 5;
    const int wloc = win & 1023;
    const int wh = wloc >> 5, ww = wloc & 31;

    for (int idx = tid; idx < 900; idx += 256) rpb_s[idx] = rpb[idx];
    if (tid < 64) lab_s[tid] = 3*region(wh*8 + (tid >> 3)) + region(ww*8 + (tid & 7));

    const unsigned xw_base = (unsigned)__cvta_generic_to_shared(Xw);
    const unsigned wb_base = (unsigned)__cvta_generic_to_shared(Wb);
    const unsigned WBB = 128*20*4;

    #define WISSUE(st_, buf_) { \
        int c_ = (st_) >> 2, ko_ = ((st_) & 3)*32; \
        _Pragma("unroll") \
        for (int s_ = 0; s_ < 2; s_++) { \
            int slot_ = tid + 256*s_; \
            int rw_ = slot_ >> 2, cc_ = slot_ & 3; \
            cp16(wb_base + (buf_)*WBB + (rw_*20 + cc_*4)*4, \
                 wqkv + (size_t)(c_*128 + rw_)*128 + ko_ + cc_*8); \
        } CP_COMMIT; }

    {
        const __nv_bfloat16* xp = xw + (size_t)win*64*128;
        #pragma unroll
        for (int s_ = 0; s_ < 4; s_++) {
            int slot = tid + 256*s_;
            int row = slot >> 4, c4 = slot & 15;
            cp16(xw_base + (row*68 + c4*4)*4, xp + (size_t)row*128 + c4*8);
        }
        WISSUE(0, 0);
    }
    WISSUE(1, 1);

    const int wm = wid >> 2;
    const int wn = wid & 3;
    const int a_row = wm*32 + lr;
    float acc[2][4][4];

    CP_WAIT1;
    __syncthreads();

    for (int st = 0; st < 12; st++) {
        if (st + 1 < 12) { WISSUE(st + 1, (st + 1) & 1); CP_WAIT1; }
        else             { CP_WAIT0; }
        if (st > 0) __syncthreads();

        if ((st & 3) == 0) {
            #pragma unroll
            for (int i = 0; i < 2; i++)
                #pragma unroll
                for (int j = 0; j < 4; j++)
                    #pragma unroll
                    for (int c = 0; c < 4; c++) acc[i][j][c] = 0.f;
        }
        {
            const unsigned* bsl = Wb + (st & 1)*128*20;
            const int koff = (st & 3)*16;
            #pragma unroll
            for (int kk2 = 0; kk2 < 16; kk2 += 8) {
                unsigned afr[2][4];
                #pragma unroll
                for (int i = 0; i < 2; i++) {
                    int base = (a_row + i*16)*68 + koff + kk2 + lc;
                    afr[i][0] = Xw[base];
                    afr[i][1] = Xw[base + 8*68];
                    afr[i][2] = Xw[base + 4];
                    afr[i][3] = Xw[base + 8*68 + 4];
                }
                #pragma unroll
                for (int j = 0; j < 4; j++) {
                    unsigned bfr[2];
                    int bb = (wn*32 + j*8 + lr)*20 + kk2 + lc;
                    bfr[0] = bsl[bb];
                    bfr[1] = bsl[bb + 4];
                    #pragma unroll
                    for (int i = 0; i < 2; i++)
                        mma_bf16(acc[i][j], afr[i], bfr);
                }
            }
        }
        if ((st & 3) == 3) {
            int chunk = st >> 2;   // 0=Q, 1=K, 2=V
            #pragma unroll
            for (int i = 0; i < 2; i++) {
                #pragma unroll
                for (int half = 0; half < 2; half++) {
                    int row = a_row + i*16 + half*8;
                    #pragma unroll
                    for (int j = 0; j < 4; j++) {
                        int n = wn*32 + j*8 + 2*lc;
                        if (chunk == 0) {
                            float v0 = (acc[i][j][half*2 + 0] + qb[n]) * scale;
                            float v1 = (acc[i][j][half*2 + 1] + qb[n+1]) * scale;
                            Qs[row*68 + wn*16 + j*4 + lc] = packbf(v0, v1);
                        } else if (chunk == 1) {
                            float v0 = acc[i][j][half*2 + 0] + kb[n];
                            float v1 = acc[i][j][half*2 + 1] + kb[n+1];
                            Ks[row*68 + wn*16 + j*4 + lc] = packbf(v0, v1);
                        } else {
                            float v0 = acc[i][j][half*2 + 0] + vb[n];
                            float v1 = acc[i][j][half*2 + 1] + vb[n+1];
                            int h0 = n >> 5,  nl0 = n & 31;
                            int h1 = (n+1) >> 5, nl1 = (n+1) & 31;
                            vtb[h0*2304 + nl0*72 + row] = bf16u(v0);
                            vtb[h1*2304 + nl1*72 + row] = bf16u(v1);
                        }
                    }
                }
            }
        }
        __syncthreads();
    }
    #undef WISSUE

    const int head = wid >> 1;
    const int w    = wid & 1;
    unsigned* Ps   = sm + AQ_PS + head*2304;
    unsigned* Vt   = sm + AQ_VT + head*1152;
    float* redm_h  = redm  + head*128;
    float* reds_h  = redsm + head*128;
    const int hq   = head*16;

    float s[4][4][4];
    #pragma unroll
    for (int i = 0; i < 4; i++)
        #pragma unroll
        for (int j = 0; j < 4; j++)
            #pragma unroll
            for (int c = 0; c < 4; c++) s[i][j][c] = 0.f;

    const int nb0 = w*32;
    #pragma unroll
    for (int kk2 = 0; kk2 < 16; kk2 += 8) {
        unsigned afr[4][4], bfr[4][2];
        #pragma unroll
        for (int i = 0; i < 4; i++) {
            int base = (i*16 + lr)*68 + hq + kk2 + lc;
            afr[i][0] = Qs[base];
            afr[i][1] = Qs[base + 8*68];
            afr[i][2] = Qs[base + 4];
            afr[i][3] = Qs[base + 8*68 + 4];
        }
        #pragma unroll
        for (int j = 0; j < 4; j++) {
            int nn = nb0 + j*8 + lr;
            bfr[j][0] = Ks[nn*68 + hq + kk2 + lc];
            bfr[j][1] = Ks[nn*68 + hq + kk2 + lc + 4];
        }
        #pragma unroll
        for (int i = 0; i < 4; i++)
            #pragma unroll
            for (int j = 0; j < 4; j++)
                mma_bf16(s[i][j], afr[i], bfr[j]);
    }

    #pragma unroll
    for (int i = 0; i < 4; i++) {
        #pragma unroll
        for (int half = 0; half < 2; half++) {
            int r = i*16 + lr + half*8;
            int labr = lab_s[r];
            int ti = r >> 3, tj = r & 7;
            float m_ = -1e30f;
            #pragma unroll
            for (int j = 0; j < 4; j++) {
                #pragma unroll
                for (int e = 0; e < 2; e++) {
                    int c = nb0 + j*8 + 2*lc + e;
                    int ki = c >> 3, kj = c & 7;
                    float val = s[i][j][half*2 + e]
                              + rpb_s[((ti - ki + 7)*15 + (tj - kj + 7))*4 + head];
                    if (lab_s[c] != labr) val -= 100.f;
                    s[i][j][half*2 + e] = val;
                    m_ = fmaxf(m_, val);
                }
            }
            m_ = fmaxf(m_, __shfl_xor_sync(0xffffffffu, m_, 1));
            m_ = fmaxf(m_, __shfl_xor_sync(0xffffffffu, m_, 2));
            if (lc == 0) redm_h[r*2 + w] = m_;
        }
    }
    __syncthreads();

    #pragma unroll
    for (int i = 0; i < 4; i++) {
        #pragma unroll
        for (int half = 0; half < 2; half++) {
            int r = i*16 + lr + half*8;
            float mx = fmaxf(redm_h[r*2], redm_h[r*2 + 1]);
            float sum = 0.f;
            #pragma unroll
            for (int j = 0; j < 4; j++) {
                float e0 = __expf(s[i][j][half*2 + 0] - mx);
                float e1 = __expf(s[i][j][half*2 + 1] - mx);
                sum += e0 + e1;
                Ps[r*36 + 16*w + j*4 + lc] = packbf(e0, e1);
            }
            sum += __shfl_xor_sync(0xffffffffu, sum, 1);
            sum += __shfl_xor_sync(0xffffffffu, sum, 2);
            if (lc == 0) reds_h[r*2 + w] = sum;
        }
    }
    __syncthreads();

    float o[2][4][4];
    #pragma unroll
    for (int i = 0; i < 2; i++)
        #pragma unroll
        for (int j = 0; j < 4; j++)
            #pragma unroll
            for (int c = 0; c < 4; c++) o[i][j][c] = 0.f;

    const int mb = w*32;
    #pragma unroll
    for (int kb = 0; kb < 4; kb++) {
        unsigned afr[2][4], bfr[4][2];
        #pragma unroll
        for (int i = 0; i < 2; i++) {
            int base = (mb + i*16 + lr)*36 + kb*8 + lc;
            afr[i][0] = Ps[base];
            afr[i][1] = Ps[base + 8*36];
            afr[i][2] = Ps[base + 4];
            afr[i][3] = Ps[base + 8*36 + 4];
        }
        #pragma unroll
        for (int j = 0; j < 4; j++) {
            int base = (j*8 + lr)*36 + kb*8 + lc;
            bfr[j][0] = Vt[base];
            bfr[j][1] = Vt[base + 4];
        }
        #pragma unroll
        for (int i = 0; i < 2; i++)
            #pragma unroll
            for (int j = 0; j < 4; j++)
                mma_bf16(o[i][j], afr[i], bfr[j]);
    }

    #pragma unroll
    for (int i = 0; i < 2; i++) {
        #pragma unroll
        for (int half = 0; half < 2; half++) {
            int r = mb + i*16 + lr + half*8;
            float inv = 1.f / (reds_h[r*2] + reds_h[r*2 + 1]);
            size_t ob = (size_t)win*64*128 + (size_t)r*128 + head*32;
            #pragma unroll
            for (int j = 0; j < 4; j++) {
                int n = j*8 + 2*lc;
                float v0 = o[i][j][half*2 + 0] * inv;
                float v1 = o[i][j][half*2 + 1] * inv;
                *(unsigned*)&out[ob + n] = packbf(v0, v1);
            }
        }
    }
}

// ---------------- fused tail: proj + LN2 + fc1+GELU + fc2, BK=64 blob ------
// 18 stages of [128][64] weights streamed linearly from g_tb.
// smem (uints): As 64*68 (aliased by Hc after proj) | L2s 64*68 | Xs f32 64*132
//               | Bs 2*128*36 | red_s 256 | red_q 256
#define T_AS 0
#define T_L2 4352
#define T_XS 8704
#define T_BS 17152
#define T_RS 26368
#define T_RQ 26624
#define TAIL_SMEM (26880*4)

__global__ void __launch_bounds__(256, 2) tail_fused(
    const __nv_bfloat16* __restrict__ ao,
    const __nv_bfloat16* __restrict__ blob,
    const float* __restrict__ pb, const float* __restrict__ b1, const float* __restrict__ b2,
    const float* __restrict__ hs,
    const float* __restrict__ gamma, const float* __restrict__ beta,
    float* __restrict__ outp)
{
    extern __shared__ unsigned sm[];
    unsigned* As  = sm + T_AS;      // also Hc after proj phase
    unsigned* L2s = sm + T_L2;
    float*    Xs  = (float*)(sm + T_XS);
    unsigned* Bs  = sm + T_BS;
    float*    red_s = (float*)(sm + T_RS);
    float*    red_q = (float*)(sm + T_RQ);
    unsigned* Hc  = As;

    const int tid  = threadIdx.x;
    const int lane = tid & 31;
    const int lr   = lane >> 2;
    const int lc   = lane & 3;
    const int w    = tid >> 5;
    const int wm   = w >> 2;
    const int wn   = w & 3;
    const int m0   = blockIdx.x * 64;
    const int a_row = wm*32 + lr;

    const unsigned bs_base = (unsigned)__cvta_generic_to_shared(Bs);
    const unsigned as_base = (unsigned)__cvta_generic_to_shared(As);
    const unsigned xs_base = (unsigned)__cvta_generic_to_shared(Xs);
    const unsigned BSB = 128*36*4;

    #define ISSUE_ST(st_, buf_) { \
        const __nv_bfloat16* W_ = blob + (size_t)(st_)*8192; \
        _Pragma("unroll") \
        for (int s_ = 0; s_ < 4; s_++) { \
            int slot_ = tid + 256*s_; \
            int rw_ = slot_ >> 3, c_ = slot_ & 7; \
            cp16(bs_base + (buf_)*BSB + (rw_*36 + c_*4)*4, W_ + rw_*64 + c_*8); \
        } CP_COMMIT; }

    // prologue: ao tile + hs[perm] rows + weight slab 0
    {
        const __nv_bfloat16* aop = ao + (size_t)m0 * 128;
        #pragma unroll
        for (int s_ = 0; s_ < 4; s_++) {
            int slot = tid + 256*s_;
            int row = slot >> 4, c4 = slot & 15;
            cp16(as_base + (row*68 + c4*4)*4, aop + (size_t)row*128 + c4*8);
        }
        #pragma unroll
        for (int s_ = 0; s_ < 8; s_++) {
            int slot = tid + 256*s_;
            int row = slot >> 5, q4 = slot & 31;
            cp16(xs_base + (row*132 + q4*4)*4,
                 hs + (size_t)perm_m(m0 + row)*128 + q4*4);
        }
        ISSUE_ST(0, 0);
    }

    float acc1[2][4][4], acc2[2][4][4];
    #pragma unroll
    for (int i = 0; i < 2; i++)
        #pragma unroll
        for (int j = 0; j < 4; j++)
            #pragma unroll
            for (int c = 0; c < 4; c++) { acc1[i][j][c] = 0.f; acc2[i][j][c] = 0.f; }

    #define STAGE_MMA(SRC, KOFF, ACC) { \
        const unsigned* bsl = Bs + (st & 1)*128*36; \
        _Pragma("unroll") \
        for (int kk2 = 0; kk2 < 32; kk2 += 8) { \
            unsigned afr[2][4]; \
            _Pragma("unroll") \
            for (int i = 0; i < 2; i++) { \
                int base = (a_row + i*16)*68 + (KOFF) + kk2 + lc; \
                afr[i][0] = SRC[base]; \
                afr[i][1] = SRC[base + 8*68]; \
                afr[i][2] = SRC[base + 4]; \
                afr[i][3] = SRC[base + 8*68 + 4]; \
            } \
            _Pragma("unroll") \
            for (int j = 0; j < 4; j++) { \
                unsigned bfr[2]; \
                int bb = (wn*32 + j*8 + lr)*36 + kk2 + lc; \
                bfr[0] = bsl[bb]; \
                bfr[1] = bsl[bb + 4]; \
                _Pragma("unroll") \
                for (int i = 0; i < 2; i++) \
                    mma_bf16(ACC[i][j], afr[i], bfr); \
            } } }

    for (int st = 0; st < 18; st++) {
        if (st + 1 < 18) { ISSUE_ST(st + 1, (st + 1) & 1); CP_WAIT1; }
        else             { CP_WAIT0; }
        __syncthreads();

        if (st < 2) {
            STAGE_MMA(As, st*32, acc1);
            if (st == 1) {
                // proj epilogue: x = acc + pb + hs; LN2 -> L2s
                #pragma unroll
                for (int i = 0; i < 2; i++) {
                    #pragma unroll
                    for (int half = 0; half < 2; half++) {
                        int row = a_row + i*16 + half*8;
                        float s = 0.f, q = 0.f;
                        #pragma unroll
                        for (int j = 0; j < 4; j++) {
                            int n = wn*32 + j*8 + 2*lc;
                            float x0 = acc1[i][j][half*2 + 0] + pb[n]   + Xs[row*132 + n];
                            float x1 = acc1[i][j][half*2 + 1] + pb[n+1] + Xs[row*132 + n + 1];
                            *(float2*)&Xs[row*132 + n] = make_float2(x0, x1);
                            s += x0 + x1;
                            q += x0*x0 + x1*x1;
                        }
                        s += __shfl_xor_sync(0xffffffffu, s, 1);
                        s += __shfl_xor_sync(0xffffffffu, s, 2);
                        q += __shfl_xor_sync(0xffffffffu, q, 1);
                        q += __shfl_xor_sync(0xffffffffu, q, 2);
                        if (lc == 0) { red_s[row*4 + wn] = s; red_q[row*4 + wn] = q; }
                    }
                }
                __syncthreads();
                #pragma unroll
                for (int i = 0; i < 2; i++) {
                    #pragma unroll
                    for (int half = 0; half < 2; half++) {
                        int row = a_row + i*16 + half*8;
                        float s = red_s[row*4+0] + red_s[row*4+1] + red_s[row*4+2] + red_s[row*4+3];
                        float q = red_q[row*4+0] + red_q[row*4+1] + red_q[row*4+2] + red_q[row*4+3];
                        float mu = s * (1.f/128.f);
                        float var = q * (1.f/128.f) - mu*mu;
                        float rstd = rsqrtf(var + 1e-5f);
                        #pragma unroll
                        for (int j = 0; j < 4; j++) {
                            int n = wn*32 + j*8 + 2*lc;
                            float x0 = Xs[row*132 + n];
                            float x1 = Xs[row*132 + n + 1];
                            float l0 = (x0 - mu)*rstd*gamma[n]   + beta[n];
                            float l1 = (x1 - mu)*rstd*gamma[n+1] + beta[n+1];
                            L2s[row*68 + wn*16 + j*4 + lc] = packbf(l0, l1);
                        }
                    }
                }
            }
        } else {
            int t = st - 2;
            int ch = t >> 2, s2 = t & 3;
            if (s2 < 2) {
                if (s2 == 0) {
                    #pragma unroll
                    for (int i = 0; i < 2; i++)
                        #pragma unroll
                        for (int j = 0; j < 4; j++)
                            #pragma unroll
                            for (int c = 0; c < 4; c++) acc1[i][j][c] = 0.f;
                }
                STAGE_MMA(L2s, s2*32, acc1);
                if (s2 == 1) {
                    // fc1 chunk epilogue: gelu -> Hc (aliases As, dead after proj)
                    #pragma unroll
                    for (int i = 0; i < 2; i++) {
                        #pragma unroll
                        for (int half = 0; half < 2; half++) {
                            int row = a_row + i*16 + half*8;
                            #pragma unroll
                            for (int j = 0; j < 4; j++) {
                                int n = wn*32 + j*8 + 2*lc;
                                float v0 = gelu_f(acc1[i][j][half*2 + 0] + b1[ch*128 + n]);
                                float v1 = gelu_f(acc1[i][j][half*2 + 1] + b1[ch*128 + n + 1]);
                                Hc[row*68 + wn*16 + j*4 + lc] = packbf(v0, v1);
                            }
                        }
                    }
                }
            } else {
                STAGE_MMA(Hc, (s2-2)*32, acc2);
            }
        }
        __syncthreads();
    }
    #undef STAGE_MMA
    #undef ISSUE_ST

    // final epilogue: out[perm(m)] = x + mlp_out + b2
    #pragma unroll
    for (int i = 0; i < 2; i++) {
        #pragma unroll
        for (int half = 0; half < 2; half++) {
            int rloc = a_row + i*16 + half*8;
            int m = m0 + rloc;
            size_t dstrow = (size_t)perm_m(m) * 128;
            #pragma unroll
            for (int j = 0; j < 4; j++) {
                int n = wn*32 + j*8 + 2*lc;
                float v0 = acc2[i][j][half*2 + 0] + b2[n]   + Xs[rloc*132 + n];
                float v1 = acc2[i][j][half*2 + 1] + b2[n+1] + Xs[rloc*132 + n + 1];
                *(float2*)&outp[dstrow + n] = make_float2(v0, v1);
            }
        }
    }
}

// ---------------------------------------------------------------------------
extern "C" void kernel_launch(void* const* d_in, const int* in_sizes, int n_in,
                              void* d_out, int out_size)
{
    const float* hs   = (const float*)d_in[0];
    const float* l1s  = (const float*)d_in[1];
    const float* l1b  = (const float*)d_in[2];
    const float* qw   = (const float*)d_in[3];
    const float* qb   = (const float*)d_in[4];
    const float* kw   = (const float*)d_in[5];
    const float* kb   = (const float*)d_in[6];
    const float* vw   = (const float*)d_in[7];
    const float* vb   = (const float*)d_in[8];
    const float* pw   = (const float*)d_in[9];
    const float* pb   = (const float*)d_in[10];
    const float* rpb  = (const float*)d_in[11];
    const float* l2s  = (const float*)d_in[12];
    const float* l2b  = (const float*)d_in[13];
    const float* f1w  = (const float*)d_in[14];
    const float* f1b  = (const float*)d_in[15];
    const float* f2w  = (const float*)d_in[16];
    const float* f2b  = (const float*)d_in[17];
    float* outp = (float*)d_out;

    __nv_bfloat16 *xw, *ao, *wt, *tb;
    cudaGetSymbolAddress((void**)&xw, g_xw);
    cudaGetSymbolAddress((void**)&ao, g_ao);
    cudaGetSymbolAddress((void**)&wt, g_wt);
    cudaGetSymbolAddress((void**)&tb, g_tb);

    cudaFuncSetAttribute(qkv_attn,   cudaFuncAttributeMaxDynamicSharedMemorySize, AQ_SMEM);
    cudaFuncSetAttribute(tail_fused, cudaFuncAttributeMaxDynamicSharedMemorySize, TAIL_SMEM);

    const float qscale = 0.17677669529663687f;  // 1/sqrt(32)

    // 0. fused weight prep (Wqkv + tail blob in consumption order)
    prep_all<<<768, 256>>>(qw, kw, vw, pw, f1w, f2w, wt, tb);
    // 1. LN1 + shift + window partition (bf16 out)
    ln_kernel<<<MTOK/8, 256>>>(hs, l1s, l1b, xw, 1);
    // 2. fused QKV + windowed attention (one block per window)
    qkv_attn<<<4096, 256, AQ_SMEM>>>(xw, wt, qb, kb, vb, rpb, qscale, ao);
    // 3. fused tail: proj + shortcut + LN2 + fc1 + GELU + fc2 + residual
    tail_fused<<<MTOK/64, 256, TAIL_SMEM>>>(ao, tb, pb, f1b, f2b,
                                            hs, l2s, l2b, outp);
}